// round 8
// baseline (speedup 1.0000x reference)
#include <cuda_runtime.h>
#include <math.h>

#define NN  100000
#define EE  1600000
#define IND 512
#define HGD 64
#define OUTD 20

#define SCAN_BLK 1024
#define NBLK ((NN + SCAN_BLK - 1) / SCAN_BLK)   // 98

typedef unsigned long long ull;

// ---------------- scratch (static device globals; no allocs) ----------------
__device__ float g_deg[NN];               // deg, then dinv (in place)
__device__ int   g_cnt[NN];               // in-degree count
__device__ int   g_rowptr[NN + 1];        // CSR offsets (by dst)
__device__ int   g_cursor[NN];            // fill cursors
__device__ int   g_bsum[NBLK];            // scan block sums
__device__ int   g_csrc[EE];              // CSR: source node per edge
__device__ float g_cnrm[EE];              // CSR: norm per edge
__device__ __align__(16) float g_xw[(size_t)NN * HGD];
__device__ __align__(16) float g_h[(size_t)NN * HGD];

__device__ __forceinline__ float selu_f(float x) {
    const float a = 1.6732632423543772f, s = 1.0507009873554805f;
    return s * (x > 0.f ? x : a * expm1f(x));
}

#define FMA2(d, a, b) asm("fma.rn.f32x2 %0, %1, %2, %0;" : "+l"(d) : "l"(a), "l"(b))
__device__ __forceinline__ void unpack2(ull v, float& lo, float& hi) {
    unsigned int l, h;
    asm("mov.b64 {%0, %1}, %2;" : "=r"(l), "=r"(h) : "l"(v));
    lo = __uint_as_float(l);
    hi = __uint_as_float(h);
}

// ---------------- degree + count ----------------
__global__ void k_deg_init() {
    int i = blockIdx.x * blockDim.x + threadIdx.x;
    if (i < NN) { g_deg[i] = 1.0f; g_cnt[i] = 0; }   // self-loop weight 1
}

__global__ void k_deg_acc(const int* __restrict__ ei, const float* __restrict__ w) {
    int e = blockIdx.x * blockDim.x + threadIdx.x;
    if (e < EE) {
        int c = ei[EE + e];
        atomicAdd(&g_deg[c], w[e]);
        atomicAdd(&g_cnt[c], 1);
    }
}

// ---------------- exclusive scan over g_cnt -> g_rowptr ----------------
__global__ void k_scan1() {
    __shared__ int sh[SCAN_BLK];
    int i = blockIdx.x * SCAN_BLK + threadIdx.x;
    int v = (i < NN) ? g_cnt[i] : 0;
    sh[threadIdx.x] = v;
    __syncthreads();
    for (int off = 1; off < SCAN_BLK; off <<= 1) {
        int t = (threadIdx.x >= off) ? sh[threadIdx.x - off] : 0;
        __syncthreads();
        sh[threadIdx.x] += t;
        __syncthreads();
    }
    if (i < NN) g_rowptr[i] = sh[threadIdx.x] - v;   // block-local exclusive
    if (threadIdx.x == SCAN_BLK - 1) g_bsum[blockIdx.x] = sh[threadIdx.x];
}

__global__ void k_scan_top() {
    __shared__ int sh[128];
    int t = threadIdx.x;
    int v = (t < NBLK) ? g_bsum[t] : 0;
    sh[t] = v;
    __syncthreads();
    for (int off = 1; off < 128; off <<= 1) {
        int u = (t >= off) ? sh[t - off] : 0;
        __syncthreads();
        sh[t] += u;
        __syncthreads();
    }
    if (t < NBLK) g_bsum[t] = sh[t] - v;   // exclusive
}

// also computes dinv (deg final after k_deg_acc)
__global__ void k_scan_add() {
    int i = blockIdx.x * SCAN_BLK + threadIdx.x;
    if (i < NN) {
        int r = g_rowptr[i] + g_bsum[blockIdx.x];
        g_rowptr[i] = r;
        g_cursor[i] = r;
        float d = g_deg[i];
        g_deg[i] = d > 0.f ? rsqrtf(fmaxf(d, 1e-30f)) : 0.f;
    }
    if (i == 0) g_rowptr[NN] = EE;
}

// ---------------- CSR fill ----------------
__global__ void k_fill(const int* __restrict__ ei, const float* __restrict__ w) {
    int e = blockIdx.x * blockDim.x + threadIdx.x;
    if (e < EE) {
        int r = ei[e];
        int c = ei[EE + e];
        int pos = atomicAdd(&g_cursor[c], 1);
        g_csrc[pos] = r;
        g_cnrm[pos] = g_deg[r] * w[e] * g_deg[c];
    }
}

// ---------------- GEMM: C[M,64] = A[M,K] @ B[K,64], FFMA2, LDS.128-clean ---
// 128-row tiles, 256 threads, 8x4 micro-tile = 4 row-pairs x 4 cols.
__global__ void k_gemm128(const float* __restrict__ A, const float* __restrict__ B,
                          float* __restrict__ C, int M, int K) {
    __shared__ __align__(16) float As[16][128];  // [k][row]
    __shared__ __align__(16) float Bs[16][128];  // [k][2*col] duplicated
    int tid = threadIdx.x;
    int tx = tid & 15;             // col group (4 cols)
    int ty = tid >> 4;             // row group (8 rows = 4 pairs)
    int row0 = blockIdx.x * 128;

    ull acc[4][4];
#pragma unroll
    for (int i = 0; i < 4; i++)
#pragma unroll
        for (int j = 0; j < 4; j++) acc[i][j] = 0ull;

    for (int kt = 0; kt < K; kt += 16) {
        // A tile: 128 rows x 16 k, transpose-store
#pragma unroll
        for (int j = 0; j < 2; j++) {
            int f4 = tid * 2 + j;
            int r = f4 >> 2;
            int kq = (f4 & 3) * 4;
            int row = row0 + r;
            float4 v = (row < M) ? *(const float4*)&A[(size_t)row * K + kt + kq]
                                 : make_float4(0.f, 0.f, 0.f, 0.f);
            As[kq + 0][r] = v.x;
            As[kq + 1][r] = v.y;
            As[kq + 2][r] = v.z;
            As[kq + 3][r] = v.w;
        }
        // B tile, duplicated: Bs[k][2c] = Bs[k][2c+1] = B[k][c]
        {
            int bk = tid >> 4, bc = (tid & 15) * 4;
            float4 v = *(const float4*)&B[(size_t)(kt + bk) * 64 + bc];
            *(float4*)&Bs[bk][bc * 2]     = make_float4(v.x, v.x, v.y, v.y);
            *(float4*)&Bs[bk][bc * 2 + 4] = make_float4(v.z, v.z, v.w, v.w);
        }
        __syncthreads();
#pragma unroll
        for (int kk = 0; kk < 16; kk++) {
            // explicit 128-bit shared loads
            float4 av0 = *(const float4*)&As[kk][ty * 8];       // rows 0..3
            float4 av1 = *(const float4*)&As[kk][ty * 8 + 4];   // rows 4..7
            float4 bv0 = *(const float4*)&Bs[kk][tx * 8];       // cols 0,1 dup'd
            float4 bv1 = *(const float4*)&Bs[kk][tx * 8 + 4];   // cols 2,3 dup'd
            ull a0 = ((const ull*)&av0)[0], a1 = ((const ull*)&av0)[1];
            ull a2 = ((const ull*)&av1)[0], a3 = ((const ull*)&av1)[1];
            ull b0 = ((const ull*)&bv0)[0], b1 = ((const ull*)&bv0)[1];
            ull b2 = ((const ull*)&bv1)[0], b3 = ((const ull*)&bv1)[1];
            FMA2(acc[0][0], a0, b0); FMA2(acc[0][1], a0, b1);
            FMA2(acc[0][2], a0, b2); FMA2(acc[0][3], a0, b3);
            FMA2(acc[1][0], a1, b0); FMA2(acc[1][1], a1, b1);
            FMA2(acc[1][2], a1, b2); FMA2(acc[1][3], a1, b3);
            FMA2(acc[2][0], a2, b0); FMA2(acc[2][1], a2, b1);
            FMA2(acc[2][2], a2, b2); FMA2(acc[2][3], a2, b3);
            FMA2(acc[3][0], a3, b0); FMA2(acc[3][1], a3, b1);
            FMA2(acc[3][2], a3, b2); FMA2(acc[3][3], a3, b3);
        }
        __syncthreads();
    }
#pragma unroll
    for (int i = 0; i < 4; i++) {
        int r0 = row0 + ty * 8 + i * 2;
        float lo[4], hi[4];
#pragma unroll
        for (int j = 0; j < 4; j++) unpack2(acc[i][j], lo[j], hi[j]);
        if (r0 < M)
            *(float4*)&C[(size_t)r0 * 64 + tx * 4] = make_float4(lo[0], lo[1], lo[2], lo[3]);
        if (r0 + 1 < M)
            *(float4*)&C[(size_t)(r0 + 1) * 64 + tx * 4] = make_float4(hi[0], hi[1], hi[2], hi[3]);
    }
}

// ---------------- CSR gather + self-loop + bias + SELU -> g_h -------------
// (round-6 version: broadcast loads, no staging)
__global__ void k_gather(const float* __restrict__ bias) {
    int t = blockIdx.x * blockDim.x + threadIdx.x;
    if (t >= NN * 16) return;
    int n = t >> 4;
    int q = (t & 15) << 2;

    float d = g_deg[n];
    float dd = d * d;
    float4 v = *(const float4*)&g_xw[(size_t)n * 64 + q];
    float4 acc = make_float4(v.x * dd, v.y * dd, v.z * dd, v.w * dd);

    int s = g_rowptr[n], e2 = g_rowptr[n + 1];
    int i = s;
    for (; i + 1 < e2; i += 2) {
        int s0 = g_csrc[i], s1 = g_csrc[i + 1];
        float n0 = g_cnrm[i], n1 = g_cnrm[i + 1];
        float4 u0 = *(const float4*)&g_xw[(size_t)s0 * 64 + q];
        float4 u1 = *(const float4*)&g_xw[(size_t)s1 * 64 + q];
        acc.x += n0 * u0.x + n1 * u1.x;
        acc.y += n0 * u0.y + n1 * u1.y;
        acc.z += n0 * u0.z + n1 * u1.z;
        acc.w += n0 * u0.w + n1 * u1.w;
    }
    if (i < e2) {
        int s0 = g_csrc[i];
        float n0 = g_cnrm[i];
        float4 u0 = *(const float4*)&g_xw[(size_t)s0 * 64 + q];
        acc.x += n0 * u0.x;
        acc.y += n0 * u0.y;
        acc.z += n0 * u0.z;
        acc.w += n0 * u0.w;
    }

    float4 b4 = *(const float4*)&bias[q];
    float4 o;
    o.x = selu_f(acc.x + b4.x);
    o.y = selu_f(acc.y + b4.y);
    o.z = selu_f(acc.z + b4.z);
    o.w = selu_f(acc.w + b4.w);
    *(float4*)&g_h[(size_t)n * 64 + q] = o;
}

// ---------------- fused dense MLP (3x 64x64 SELU + 64x20) + softmax --------
// (round-6 version)
__global__ void k_dense(const float* __restrict__ w0, const float* __restrict__ b0,
                        const float* __restrict__ w1, const float* __restrict__ b1,
                        const float* __restrict__ w2, const float* __restrict__ b2,
                        const float* __restrict__ w3, const float* __restrict__ b3,
                        float* __restrict__ out) {
    __shared__ float Ws[64][64];
    __shared__ float hs[16][64];
    __shared__ float lg[16][20];
    __shared__ float bs[64];

    int tid = threadIdx.x;
    int j = tid & 63, rq = tid >> 6;
    int row0 = blockIdx.x * 16;

    for (int i = tid; i < 16 * 64; i += 256) {
        int r = i >> 6, f = i & 63;
        int row = row0 + r;
        hs[r][f] = (row < NN) ? g_h[(size_t)row * 64 + f] : 0.f;
    }

    const float* Wp[3] = {w0, w1, w2};
    const float* Bp[3] = {b0, b1, b2};

    for (int L = 0; L < 3; L++) {
        __syncthreads();
        for (int i = tid; i < 4096; i += 256) Ws[i >> 6][i & 63] = Wp[L][i];
        if (tid < 64) bs[tid] = Bp[L][tid];
        __syncthreads();
        float acc[4];
#pragma unroll
        for (int i = 0; i < 4; i++) acc[i] = bs[j];
        for (int k = 0; k < 64; k++) {
            float wv = Ws[k][j];
#pragma unroll
            for (int i = 0; i < 4; i++) acc[i] += hs[rq * 4 + i][k] * wv;
        }
        __syncthreads();
#pragma unroll
        for (int i = 0; i < 4; i++) hs[rq * 4 + i][j] = selu_f(acc[i]);
    }

    __syncthreads();
    for (int i = tid; i < 64 * 20; i += 256) Ws[i / 20][i % 20] = w3[i];
    if (tid < 20) bs[tid] = b3[tid];
    __syncthreads();

    if (j < 20) {
        float acc[4];
#pragma unroll
        for (int i = 0; i < 4; i++) acc[i] = bs[j];
        for (int k = 0; k < 64; k++) {
            float wv = Ws[k][j];
#pragma unroll
            for (int i = 0; i < 4; i++) acc[i] += hs[rq * 4 + i][k] * wv;
        }
#pragma unroll
        for (int i = 0; i < 4; i++) lg[rq * 4 + i][j] = acc[i];
    }
    __syncthreads();

    for (int idx = tid; idx < 16 * 20; idx += 256) {
        int r = idx / 20, jj = idx % 20;
        int row = row0 + r;
        if (row < NN) {
            float mx = -1e30f;
#pragma unroll
            for (int k = 0; k < 20; k++) mx = fmaxf(mx, lg[r][k]);
            float s = 0.f;
#pragma unroll
            for (int k = 0; k < 20; k++) s += expf(lg[r][k] - mx);
            out[(size_t)row * 20 + jj] = expf(lg[r][jj] - mx) / s;
        }
    }
}

// ---------------- launch ----------------
extern "C" void kernel_launch(void* const* d_in, const int* in_sizes, int n_in,
                              void* d_out, int out_size) {
    const float* x    = (const float*)d_in[0];
    const int*   ei   = (const int*)d_in[1];      // int32 (JAX x64 disabled)
    const float* ea   = (const float*)d_in[2];
    const float* gc0w = (const float*)d_in[3];
    const float* gc0b = (const float*)d_in[4];
    const float* gc1w = (const float*)d_in[5];
    const float* gc1b = (const float*)d_in[6];
    const float* l0w  = (const float*)d_in[7];
    const float* l0b  = (const float*)d_in[8];
    const float* l1w  = (const float*)d_in[9];
    const float* l1b  = (const float*)d_in[10];
    const float* l2w  = (const float*)d_in[11];
    const float* l2b  = (const float*)d_in[12];
    const float* l3w  = (const float*)d_in[13];
    const float* l3b  = (const float*)d_in[14];
    float*       out  = (float*)d_out;

    float *xw, *h;
    cudaGetSymbolAddress((void**)&xw, g_xw);
    cudaGetSymbolAddress((void**)&h,  g_h);

    const int T = 256;

    // normalization + CSR build (reused by both convs)
    k_deg_init<<<(NN + T - 1) / T, T>>>();
    k_deg_acc<<<(EE + T - 1) / T, T>>>(ei, ea);
    k_scan1<<<NBLK, SCAN_BLK>>>();
    k_scan_top<<<1, 128>>>();
    k_scan_add<<<NBLK, SCAN_BLK>>>();
    k_fill<<<(EE + T - 1) / T, T>>>(ei, ea);

    // conv 0
    k_gemm128<<<(NN + 127) / 128, T>>>(x, gc0w, xw, NN, IND);
    k_gather<<<(NN * 16 + T - 1) / T, T>>>(gc0b);

    // conv 1
    k_gemm128<<<(NN + 127) / 128, T>>>(h, gc1w, xw, NN, HGD);
    k_gather<<<(NN * 16 + T - 1) / T, T>>>(gc1b);

    // dense stack + softmax
    k_dense<<<(NN + 15) / 16, T>>>(l0w, l0b, l1w, l1b, l2w, l2b, l3w, l3b, out);
}

// round 10
// speedup vs baseline: 1.4216x; 1.4216x over previous
#include <cuda_runtime.h>
#include <cuda_bf16.h>
#include <math.h>
#include <stdint.h>

#define NN  100000
#define EE  1600000
#define IND 512
#define HGD 64
#define OUTD 20

#define SCAN_BLK 1024
#define NBLK ((NN + SCAN_BLK - 1) / SCAN_BLK)   // 98

typedef unsigned long long ull;

// ---------------- scratch (static device globals; no allocs) ----------------
__device__ float g_deg[NN];               // deg, then dinv (in place)
__device__ int   g_cnt[NN];
__device__ int   g_rowptr[NN + 1];
__device__ int   g_cursor[NN];
__device__ int   g_bsum[NBLK];
__device__ int   g_csrc[EE];
__device__ float g_cnrm[EE];
__device__ __align__(16) float g_xw[(size_t)NN * HGD];
__device__ __align__(16) float g_h[(size_t)NN * HGD];
// gc0_w split-bf16 images, [n][k] layout (n=0..63, k=0..511)
__device__ __align__(16) __nv_bfloat16 g_wbh[64 * 512];
__device__ __align__(16) __nv_bfloat16 g_wbl[64 * 512];

__device__ __forceinline__ float selu_f(float x) {
    const float a = 1.6732632423543772f, s = 1.0507009873554805f;
    return s * (x > 0.f ? x : a * expm1f(x));
}

// warp-level bf16 MMA (sm_80+ PTX; valid on compute_103 baseline target)
__device__ __forceinline__ void mma_bf16(float* c, const uint32_t* a, uint32_t b0, uint32_t b1) {
    asm volatile(
        "mma.sync.aligned.m16n8k16.row.col.f32.bf16.bf16.f32 "
        "{%0,%1,%2,%3}, {%4,%5,%6,%7}, {%8,%9}, {%0,%1,%2,%3};"
        : "+f"(c[0]), "+f"(c[1]), "+f"(c[2]), "+f"(c[3])
        : "r"(a[0]), "r"(a[1]), "r"(a[2]), "r"(a[3]), "r"(b0), "r"(b1));
}

// ---------------- degree + count ----------------
__global__ void k_deg_init() {
    int i = blockIdx.x * blockDim.x + threadIdx.x;
    if (i < NN) { g_deg[i] = 1.0f; g_cnt[i] = 0; }
}

__global__ void k_deg_acc(const int* __restrict__ ei, const float* __restrict__ w) {
    int e = blockIdx.x * blockDim.x + threadIdx.x;
    if (e < EE) {
        int c = ei[EE + e];
        atomicAdd(&g_deg[c], w[e]);
        atomicAdd(&g_cnt[c], 1);
    }
}

// ---------------- exclusive scan over g_cnt -> g_rowptr ----------------
__global__ void k_scan1() {
    __shared__ int sh[SCAN_BLK];
    int i = blockIdx.x * SCAN_BLK + threadIdx.x;
    int v = (i < NN) ? g_cnt[i] : 0;
    sh[threadIdx.x] = v;
    __syncthreads();
    for (int off = 1; off < SCAN_BLK; off <<= 1) {
        int t = (threadIdx.x >= off) ? sh[threadIdx.x - off] : 0;
        __syncthreads();
        sh[threadIdx.x] += t;
        __syncthreads();
    }
    if (i < NN) g_rowptr[i] = sh[threadIdx.x] - v;
    if (threadIdx.x == SCAN_BLK - 1) g_bsum[blockIdx.x] = sh[threadIdx.x];
}

__global__ void k_scan_top() {
    __shared__ int sh[128];
    int t = threadIdx.x;
    int v = (t < NBLK) ? g_bsum[t] : 0;
    sh[t] = v;
    __syncthreads();
    for (int off = 1; off < 128; off <<= 1) {
        int u = (t >= off) ? sh[t - off] : 0;
        __syncthreads();
        sh[t] += u;
        __syncthreads();
    }
    if (t < NBLK) g_bsum[t] = sh[t] - v;
}

__global__ void k_scan_add() {
    int i = blockIdx.x * SCAN_BLK + threadIdx.x;
    if (i < NN) {
        int r = g_rowptr[i] + g_bsum[blockIdx.x];
        g_rowptr[i] = r;
        g_cursor[i] = r;
        float d = g_deg[i];
        g_deg[i] = d > 0.f ? rsqrtf(fmaxf(d, 1e-30f)) : 0.f;
    }
    if (i == 0) g_rowptr[NN] = EE;
}

// ---------------- CSR fill ----------------
__global__ void k_fill(const int* __restrict__ ei, const float* __restrict__ w) {
    int e = blockIdx.x * blockDim.x + threadIdx.x;
    if (e < EE) {
        int r = ei[e];
        int c = ei[EE + e];
        int pos = atomicAdd(&g_cursor[c], 1);
        g_csrc[pos] = r;
        g_cnrm[pos] = g_deg[r] * w[e] * g_deg[c];
    }
}

// ---------------- W -> split-bf16 images, [n][k] ----------------------------
__global__ void k_wb(const float* __restrict__ W) {
    int i = blockIdx.x * blockDim.x + threadIdx.x;
    if (i >= 512 * 64) return;
    int k = i >> 6, n = i & 63;     // i == k*64+n == index into W
    float w = W[i];
    __nv_bfloat16 hi = __float2bfloat16(w);
    __nv_bfloat16 lo = __float2bfloat16(w - __bfloat162float(hi));
    g_wbh[n * 512 + k] = hi;
    g_wbl[n * 512 + k] = lo;
}

// ---------------- conv0 GEMM on mma.sync bf16, split-bf16 3-term ------------
// C[M,64] = A[M,512] @ W. 256 threads = 8 warps, each warp one 16x64 stripe.
// K chunked by 64. Smem strides = 72 bf16 (144B, conflict-free: bank=4*gr+t).
#define ASTR 72
#define SM_AHI_O 0
#define SM_ALO_O 18432
#define SM_BHI_O 36864
#define SM_BLO_O 46080
#define SM_MMA_TOT 55296
__global__ void k_conv0_mma(const float* __restrict__ A, float* __restrict__ C, int M) {
    extern __shared__ __align__(16) char smem[];
    __nv_bfloat16* Ah = (__nv_bfloat16*)(smem + SM_AHI_O);
    __nv_bfloat16* Al = (__nv_bfloat16*)(smem + SM_ALO_O);
    __nv_bfloat16* Bh = (__nv_bfloat16*)(smem + SM_BHI_O);
    __nv_bfloat16* Bl = (__nv_bfloat16*)(smem + SM_BLO_O);

    int tid = threadIdx.x;
    int w = tid >> 5, lane = tid & 31;
    int gr = lane >> 2, t = lane & 3;
    int row0 = blockIdx.x * 128;

    float acc[8][4];
#pragma unroll
    for (int i = 0; i < 8; i++)
#pragma unroll
        for (int j = 0; j < 4; j++) acc[i][j] = 0.f;

    for (int c = 0; c < 8; c++) {
        // ---- A chunk [128 x 64] fp32 -> bf16 hi/lo into smem
#pragma unroll
        for (int it = 0; it < 8; it++) {
            int idx = tid + it * 256;      // 0..2047 float4s
            int r = idx >> 4;              // 0..127
            int kq = (idx & 15) * 4;       // 0..60
            int row = row0 + r;
            float4 v = (row < M) ? *(const float4*)&A[(size_t)row * 512 + c * 64 + kq]
                                 : make_float4(0.f, 0.f, 0.f, 0.f);
            __nv_bfloat16 hx = __float2bfloat16(v.x), hy = __float2bfloat16(v.y);
            __nv_bfloat16 hz = __float2bfloat16(v.z), hw = __float2bfloat16(v.w);
            __nv_bfloat162 h0; h0.x = hx; h0.y = hy;
            __nv_bfloat162 h1; h1.x = hz; h1.y = hw;
            __nv_bfloat162 l0; l0.x = __float2bfloat16(v.x - __bfloat162float(hx));
                               l0.y = __float2bfloat16(v.y - __bfloat162float(hy));
            __nv_bfloat162 l1; l1.x = __float2bfloat16(v.z - __bfloat162float(hz));
                               l1.y = __float2bfloat16(v.w - __bfloat162float(hw));
            int so = r * ASTR + kq;
            *(__nv_bfloat162*)(Ah + so)     = h0;
            *(__nv_bfloat162*)(Ah + so + 2) = h1;
            *(__nv_bfloat162*)(Al + so)     = l0;
            *(__nv_bfloat162*)(Al + so + 2) = l1;
        }
        // ---- B chunk [64 x 64] bf16 hi/lo copy from gmem images
#pragma unroll
        for (int it = 0; it < 2; it++) {
            int i = tid + it * 256;        // 0..511
            int n = i >> 3, j = i & 7;     // row, uint4-within-row
            uint4 vh = *((const uint4*)(g_wbh + n * 512 + c * 64) + j);
            uint4 vl = *((const uint4*)(g_wbl + n * 512 + c * 64) + j);
            *((uint4*)((char*)Bh + n * 144) + j) = vh;
            *((uint4*)((char*)Bl + n * 144) + j) = vl;
        }
        __syncthreads();

        // ---- compute: 4 k-steps x 8 n-tiles x 3 terms
        const __nv_bfloat16* arh = Ah + (w * 16 + gr) * ASTR;
        const __nv_bfloat16* arl = Al + (w * 16 + gr) * ASTR;
#pragma unroll
        for (int ks = 0; ks < 4; ks++) {
            int k0 = ks * 16 + t * 2;
            uint32_t ah[4], al[4];
            ah[0] = *(const uint32_t*)(arh + k0);
            ah[1] = *(const uint32_t*)(arh + 8 * ASTR + k0);
            ah[2] = *(const uint32_t*)(arh + k0 + 8);
            ah[3] = *(const uint32_t*)(arh + 8 * ASTR + k0 + 8);
            al[0] = *(const uint32_t*)(arl + k0);
            al[1] = *(const uint32_t*)(arl + 8 * ASTR + k0);
            al[2] = *(const uint32_t*)(arl + k0 + 8);
            al[3] = *(const uint32_t*)(arl + 8 * ASTR + k0 + 8);
#pragma unroll
            for (int nt = 0; nt < 8; nt++) {
                const __nv_bfloat16* bph = Bh + (nt * 8 + gr) * ASTR + k0;
                uint32_t bh0 = *(const uint32_t*)bph;
                uint32_t bh1 = *(const uint32_t*)(bph + 8);
                mma_bf16(acc[nt], ah, bh0, bh1);
                mma_bf16(acc[nt], al, bh0, bh1);
                const __nv_bfloat16* bpl = Bl + (nt * 8 + gr) * ASTR + k0;
                uint32_t bl0 = *(const uint32_t*)bpl;
                uint32_t bl1 = *(const uint32_t*)(bpl + 8);
                mma_bf16(acc[nt], ah, bl0, bl1);
            }
        }
        __syncthreads();
    }

    // ---- epilogue: fragment layout c0..c3 -> rows (gr, gr+8), cols (2t, 2t+1)
    int r1 = row0 + w * 16 + gr;
    int r2 = r1 + 8;
#pragma unroll
    for (int nt = 0; nt < 8; nt++) {
        int col = nt * 8 + t * 2;
        if (r1 < M) *(float2*)&C[(size_t)r1 * 64 + col] = make_float2(acc[nt][0], acc[nt][1]);
        if (r2 < M) *(float2*)&C[(size_t)r2 * 64 + col] = make_float2(acc[nt][2], acc[nt][3]);
    }
}

// ---------------- fp32 GEMM (round-6, conv1 K=64) --------------------------
__global__ void k_gemm128(const float* __restrict__ A, const float* __restrict__ B,
                          float* __restrict__ C, int M, int K) {
    __shared__ float As[16][128];
    __shared__ float Bs[16][64];
    int tid = threadIdx.x;
    int tx = tid & 15;
    int ty = tid >> 4;
    int row0 = blockIdx.x * 128;

    float acc[8][4] = {};

    for (int kt = 0; kt < K; kt += 16) {
#pragma unroll
        for (int j = 0; j < 2; j++) {
            int f4 = tid * 2 + j;
            int r = f4 >> 2;
            int kq = (f4 & 3) * 4;
            int row = row0 + r;
            float4 v = (row < M) ? *(const float4*)&A[(size_t)row * K + kt + kq]
                                 : make_float4(0.f, 0.f, 0.f, 0.f);
            As[kq + 0][r] = v.x;
            As[kq + 1][r] = v.y;
            As[kq + 2][r] = v.z;
            As[kq + 3][r] = v.w;
        }
        {
            int bk = tid >> 4, bc = (tid & 15) * 4;
            *(float4*)&Bs[bk][bc] = *(const float4*)&B[(size_t)(kt + bk) * 64 + bc];
        }
        __syncthreads();
#pragma unroll
        for (int kk = 0; kk < 16; kk++) {
            float4 a0 = *(const float4*)&As[kk][ty * 8];
            float4 a1 = *(const float4*)&As[kk][ty * 8 + 4];
            float4 b  = *(const float4*)&Bs[kk][tx * 4];
            float av[8] = {a0.x, a0.y, a0.z, a0.w, a1.x, a1.y, a1.z, a1.w};
            float bv[4] = {b.x, b.y, b.z, b.w};
#pragma unroll
            for (int i = 0; i < 8; i++)
#pragma unroll
                for (int j = 0; j < 4; j++)
                    acc[i][j] += av[i] * bv[j];
        }
        __syncthreads();
    }
#pragma unroll
    for (int i = 0; i < 8; i++) {
        int row = row0 + ty * 8 + i;
        if (row < M) {
            float4 v = make_float4(acc[i][0], acc[i][1], acc[i][2], acc[i][3]);
            *(float4*)&C[(size_t)row * 64 + tx * 4] = v;
        }
    }
}

// ---------------- CSR gather + self-loop + bias + SELU -> g_h (round-6) ----
__global__ void k_gather(const float* __restrict__ bias) {
    int t = blockIdx.x * blockDim.x + threadIdx.x;
    if (t >= NN * 16) return;
    int n = t >> 4;
    int q = (t & 15) << 2;

    float d = g_deg[n];
    float dd = d * d;
    float4 v = *(const float4*)&g_xw[(size_t)n * 64 + q];
    float4 acc = make_float4(v.x * dd, v.y * dd, v.z * dd, v.w * dd);

    int s = g_rowptr[n], e2 = g_rowptr[n + 1];
    int i = s;
    for (; i + 1 < e2; i += 2) {
        int s0 = g_csrc[i], s1 = g_csrc[i + 1];
        float n0 = g_cnrm[i], n1 = g_cnrm[i + 1];
        float4 u0 = *(const float4*)&g_xw[(size_t)s0 * 64 + q];
        float4 u1 = *(const float4*)&g_xw[(size_t)s1 * 64 + q];
        acc.x += n0 * u0.x + n1 * u1.x;
        acc.y += n0 * u0.y + n1 * u1.y;
        acc.z += n0 * u0.z + n1 * u1.z;
        acc.w += n0 * u0.w + n1 * u1.w;
    }
    if (i < e2) {
        int s0 = g_csrc[i];
        float n0 = g_cnrm[i];
        float4 u0 = *(const float4*)&g_xw[(size_t)s0 * 64 + q];
        acc.x += n0 * u0.x;
        acc.y += n0 * u0.y;
        acc.z += n0 * u0.z;
        acc.w += n0 * u0.w;
    }

    float4 b4 = *(const float4*)&bias[q];
    float4 o;
    o.x = selu_f(acc.x + b4.x);
    o.y = selu_f(acc.y + b4.y);
    o.z = selu_f(acc.z + b4.z);
    o.w = selu_f(acc.w + b4.w);
    *(float4*)&g_h[(size_t)n * 64 + q] = o;
}

// ---------------- fused dense MLP + softmax (round-6) ----------------------
__global__ void k_dense(const float* __restrict__ w0, const float* __restrict__ b0,
                        const float* __restrict__ w1, const float* __restrict__ b1,
                        const float* __restrict__ w2, const float* __restrict__ b2,
                        const float* __restrict__ w3, const float* __restrict__ b3,
                        float* __restrict__ out) {
    __shared__ float Ws[64][64];
    __shared__ float hs[16][64];
    __shared__ float lg[16][20];
    __shared__ float bs[64];

    int tid = threadIdx.x;
    int j = tid & 63, rq = tid >> 6;
    int row0 = blockIdx.x * 16;

    for (int i = tid; i < 16 * 64; i += 256) {
        int r = i >> 6, f = i & 63;
        int row = row0 + r;
        hs[r][f] = (row < NN) ? g_h[(size_t)row * 64 + f] : 0.f;
    }

    const float* Wp[3] = {w0, w1, w2};
    const float* Bp[3] = {b0, b1, b2};

    for (int L = 0; L < 3; L++) {
        __syncthreads();
        for (int i = tid; i < 4096; i += 256) Ws[i >> 6][i & 63] = Wp[L][i];
        if (tid < 64) bs[tid] = Bp[L][tid];
        __syncthreads();
        float acc[4];
#pragma unroll
        for (int i = 0; i < 4; i++) acc[i] = bs[j];
        for (int k = 0; k < 64; k++) {
            float wv = Ws[k][j];
#pragma unroll
            for (int i = 0; i < 4; i++) acc[i] += hs[rq * 4 + i][k] * wv;
        }
        __syncthreads();
#pragma unroll
        for (int i = 0; i < 4; i++) hs[rq * 4 + i][j] = selu_f(acc[i]);
    }

    __syncthreads();
    for (int i = tid; i < 64 * 20; i += 256) Ws[i / 20][i % 20] = w3[i];
    if (tid < 20) bs[tid] = b3[tid];
    __syncthreads();

    if (j < 20) {
        float acc[4];
#pragma unroll
        for (int i = 0; i < 4; i++) acc[i] = bs[j];
        for (int k = 0; k < 64; k++) {
            float wv = Ws[k][j];
#pragma unroll
            for (int i = 0; i < 4; i++) acc[i] += hs[rq * 4 + i][k] * wv;
        }
#pragma unroll
        for (int i = 0; i < 4; i++) lg[rq * 4 + i][j] = acc[i];
    }
    __syncthreads();

    for (int idx = tid; idx < 16 * 20; idx += 256) {
        int r = idx / 20, jj = idx % 20;
        int row = row0 + r;
        if (row < NN) {
            float mx = -1e30f;
#pragma unroll
            for (int k = 0; k < 20; k++) mx = fmaxf(mx, lg[r][k]);
            float s = 0.f;
#pragma unroll
            for (int k = 0; k < 20; k++) s += expf(lg[r][k] - mx);
            out[(size_t)row * 20 + jj] = expf(lg[r][jj] - mx) / s;
        }
    }
}

// ---------------- launch ----------------
extern "C" void kernel_launch(void* const* d_in, const int* in_sizes, int n_in,
                              void* d_out, int out_size) {
    const float* x    = (const float*)d_in[0];
    const int*   ei   = (const int*)d_in[1];      // int32 (JAX x64 disabled)
    const float* ea   = (const float*)d_in[2];
    const float* gc0w = (const float*)d_in[3];
    const float* gc0b = (const float*)d_in[4];
    const float* gc1w = (const float*)d_in[5];
    const float* gc1b = (const float*)d_in[6];
    const float* l0w  = (const float*)d_in[7];
    const float* l0b  = (const float*)d_in[8];
    const float* l1w  = (const float*)d_in[9];
    const float* l1b  = (const float*)d_in[10];
    const float* l2w  = (const float*)d_in[11];
    const float* l2b  = (const float*)d_in[12];
    const float* l3w  = (const float*)d_in[13];
    const float* l3b  = (const float*)d_in[14];
    float*       out  = (float*)d_out;

    float *xw, *h;
    cudaGetSymbolAddress((void**)&xw, g_xw);
    cudaGetSymbolAddress((void**)&h,  g_h);

    cudaFuncSetAttribute(k_conv0_mma, cudaFuncAttributeMaxDynamicSharedMemorySize, SM_MMA_TOT);

    const int T = 256;

    // normalization + CSR build + W split-bf16 images
    k_deg_init<<<(NN + T - 1) / T, T>>>();
    k_deg_acc<<<(EE + T - 1) / T, T>>>(ei, ea);
    k_scan1<<<NBLK, SCAN_BLK>>>();
    k_scan_top<<<1, 128>>>();
    k_scan_add<<<NBLK, SCAN_BLK>>>();
    k_fill<<<(EE + T - 1) / T, T>>>(ei, ea);
    k_wb<<<(512 * 64 + T - 1) / T, T>>>(gc0w);

    // conv 0: tensor-core (mma.sync bf16 split) GEMM
    k_conv0_mma<<<(NN + 127) / 128, T, SM_MMA_TOT>>>(x, xw, NN);
    k_gather<<<(NN * 16 + T - 1) / T, T>>>(gc0b);

    // conv 1: fp32 GEMM (K=64)
    k_gemm128<<<(NN + 127) / 128, T>>>(h, gc1w, xw, NN, HGD);
    k_gather<<<(NN * 16 + T - 1) / T, T>>>(gc1b);

    // dense stack + softmax
    k_dense<<<(NN + 15) / 16, T>>>(l0w, l0b, l1w, l1b, l2w, l2b, l3w, l3b, out);
}

// round 11
// speedup vs baseline: 1.5577x; 1.0958x over previous
#include <cuda_runtime.h>
#include <cuda_bf16.h>
#include <math.h>
#include <stdint.h>

#define NN  100000
#define EE  1600000
#define IND 512
#define HGD 64
#define OUTD 20

#define SCAN_BLK 1024
#define NBLK ((NN + SCAN_BLK - 1) / SCAN_BLK)   // 98

typedef unsigned long long ull;

// ---------------- scratch (static device globals; no allocs) ----------------
__device__ float g_deg[NN];               // deg, then dinv (in place)
__device__ int   g_cnt[NN];
__device__ int   g_rowptr[NN + 1];
__device__ int   g_cursor[NN];
__device__ int   g_bsum[NBLK];
__device__ int   g_csrc[EE];
__device__ float g_cnrm[EE];
__device__ __align__(16) float g_xw[(size_t)NN * HGD];
__device__ __align__(16) float g_h[(size_t)NN * HGD];
// gc0_w split-bf16 images, [n][k] layout (n=0..63, k=0..511)
__device__ __align__(16) __nv_bfloat16 g_wbh[64 * 512];
__device__ __align__(16) __nv_bfloat16 g_wbl[64 * 512];

__device__ __forceinline__ float selu_f(float x) {
    const float a = 1.6732632423543772f, s = 1.0507009873554805f;
    return s * (x > 0.f ? x : a * expm1f(x));
}

// warp-level bf16 MMA (sm_80+ PTX; valid on compute_103 baseline target)
__device__ __forceinline__ void mma_bf16(float* c, const uint32_t* a, uint32_t b0, uint32_t b1) {
    asm volatile(
        "mma.sync.aligned.m16n8k16.row.col.f32.bf16.bf16.f32 "
        "{%0,%1,%2,%3}, {%4,%5,%6,%7}, {%8,%9}, {%0,%1,%2,%3};"
        : "+f"(c[0]), "+f"(c[1]), "+f"(c[2]), "+f"(c[3])
        : "r"(a[0]), "r"(a[1]), "r"(a[2]), "r"(a[3]), "r"(b0), "r"(b1));
}

__device__ __forceinline__ void ldsm4(uint32_t* r, uint32_t addr) {
    asm volatile("ldmatrix.sync.aligned.m8n8.x4.shared.b16 {%0,%1,%2,%3}, [%4];"
                 : "=r"(r[0]), "=r"(r[1]), "=r"(r[2]), "=r"(r[3]) : "r"(addr));
}

__device__ __forceinline__ uint32_t smem_u32(const void* p) {
    uint32_t a;
    asm("{ .reg .u64 t; cvta.to.shared.u64 t, %1; cvt.u32.u64 %0, t; }" : "=r"(a) : "l"(p));
    return a;
}

// ---------------- degree + count ----------------
__global__ void k_deg_init() {
    int i = blockIdx.x * blockDim.x + threadIdx.x;
    if (i < NN) { g_deg[i] = 1.0f; g_cnt[i] = 0; }
}

__global__ void k_deg_acc(const int* __restrict__ ei, const float* __restrict__ w) {
    int e = blockIdx.x * blockDim.x + threadIdx.x;
    if (e < EE) {
        int c = ei[EE + e];
        atomicAdd(&g_deg[c], w[e]);
        atomicAdd(&g_cnt[c], 1);
    }
}

// ---------------- exclusive scan over g_cnt -> g_rowptr ----------------
__global__ void k_scan1() {
    __shared__ int sh[SCAN_BLK];
    int i = blockIdx.x * SCAN_BLK + threadIdx.x;
    int v = (i < NN) ? g_cnt[i] : 0;
    sh[threadIdx.x] = v;
    __syncthreads();
    for (int off = 1; off < SCAN_BLK; off <<= 1) {
        int t = (threadIdx.x >= off) ? sh[threadIdx.x - off] : 0;
        __syncthreads();
        sh[threadIdx.x] += t;
        __syncthreads();
    }
    if (i < NN) g_rowptr[i] = sh[threadIdx.x] - v;
    if (threadIdx.x == SCAN_BLK - 1) g_bsum[blockIdx.x] = sh[threadIdx.x];
}

__global__ void k_scan_top() {
    __shared__ int sh[128];
    int t = threadIdx.x;
    int v = (t < NBLK) ? g_bsum[t] : 0;
    sh[t] = v;
    __syncthreads();
    for (int off = 1; off < 128; off <<= 1) {
        int u = (t >= off) ? sh[t - off] : 0;
        __syncthreads();
        sh[t] += u;
        __syncthreads();
    }
    if (t < NBLK) g_bsum[t] = sh[t] - v;
}

__global__ void k_scan_add() {
    int i = blockIdx.x * SCAN_BLK + threadIdx.x;
    if (i < NN) {
        int r = g_rowptr[i] + g_bsum[blockIdx.x];
        g_rowptr[i] = r;
        g_cursor[i] = r;
        float d = g_deg[i];
        g_deg[i] = d > 0.f ? rsqrtf(fmaxf(d, 1e-30f)) : 0.f;
    }
    if (i == 0) g_rowptr[NN] = EE;
}

// ---------------- CSR fill ----------------
__global__ void k_fill(const int* __restrict__ ei, const float* __restrict__ w) {
    int e = blockIdx.x * blockDim.x + threadIdx.x;
    if (e < EE) {
        int r = ei[e];
        int c = ei[EE + e];
        int pos = atomicAdd(&g_cursor[c], 1);
        g_csrc[pos] = r;
        g_cnrm[pos] = g_deg[r] * w[e] * g_deg[c];
    }
}

// ---------------- W -> split-bf16 images, [n][k] ----------------------------
__global__ void k_wb(const float* __restrict__ W) {
    int i = blockIdx.x * blockDim.x + threadIdx.x;
    if (i >= 512 * 64) return;
    int k = i >> 6, n = i & 63;
    float w = W[i];
    __nv_bfloat16 hi = __float2bfloat16(w);
    __nv_bfloat16 lo = __float2bfloat16(w - __bfloat162float(hi));
    g_wbh[n * 512 + k] = hi;
    g_wbl[n * 512 + k] = lo;
}

// ---------------- conv0 GEMM on mma.sync bf16, split-bf16, ldmatrix --------
// C[M,64] = A[M,512] @ W. 256 threads = 8 warps, each warp one 16x64 stripe.
// K chunked by 64. Smem row strides = 72 bf16 (144B, ldmatrix conflict-free).
#define ASTR 72
#define SM_AHI_O 0
#define SM_ALO_O 18432
#define SM_BHI_O 36864
#define SM_BLO_O 46080
#define SM_MMA_TOT 55296
__global__ void k_conv0_mma(const float* __restrict__ A, float* __restrict__ C, int M) {
    extern __shared__ __align__(16) char smem[];
    __nv_bfloat16* Ah = (__nv_bfloat16*)(smem + SM_AHI_O);
    __nv_bfloat16* Al = (__nv_bfloat16*)(smem + SM_ALO_O);
    __nv_bfloat16* Bh = (__nv_bfloat16*)(smem + SM_BHI_O);
    __nv_bfloat16* Bl = (__nv_bfloat16*)(smem + SM_BLO_O);

    int tid = threadIdx.x;
    int w = tid >> 5, lane = tid & 31;
    int gr = lane >> 2, t = lane & 3;
    int row0 = blockIdx.x * 128;
    uint32_t sb = smem_u32(smem);

    // ldmatrix per-lane byte offsets (within each region), ks-invariant parts
    // A 16x16 tile: row = w*16 + (lane&7) + ((lane>>3)&1)*8, k-half = (lane>>4)*8
    uint32_t a_off = (uint32_t)((w * 16 + (lane & 7) + ((lane >> 3) & 1) * 8) * 144
                                + ((lane >> 4) & 1) * 16);
    // B pair p covers n-tiles 2p,2p+1: n-row = p*16 + ((lane>>4)&1)*8 + (lane&7),
    // k-half = ((lane>>3)&1)*8
    uint32_t b_off_base = (uint32_t)((((lane >> 4) & 1) * 8 + (lane & 7)) * 144
                                     + ((lane >> 3) & 1) * 16);

    float acc[8][4];
#pragma unroll
    for (int i = 0; i < 8; i++)
#pragma unroll
        for (int j = 0; j < 4; j++) acc[i][j] = 0.f;

    for (int c = 0; c < 8; c++) {
        // ---- A chunk [128 x 64] fp32 -> bf16 hi/lo into smem
#pragma unroll
        for (int it = 0; it < 8; it++) {
            int idx = tid + it * 256;
            int r = idx >> 4;
            int kq = (idx & 15) * 4;
            int row = row0 + r;
            float4 v = (row < M) ? *(const float4*)&A[(size_t)row * 512 + c * 64 + kq]
                                 : make_float4(0.f, 0.f, 0.f, 0.f);
            __nv_bfloat16 hx = __float2bfloat16(v.x), hy = __float2bfloat16(v.y);
            __nv_bfloat16 hz = __float2bfloat16(v.z), hw = __float2bfloat16(v.w);
            __nv_bfloat162 h0; h0.x = hx; h0.y = hy;
            __nv_bfloat162 h1; h1.x = hz; h1.y = hw;
            __nv_bfloat162 l0; l0.x = __float2bfloat16(v.x - __bfloat162float(hx));
                               l0.y = __float2bfloat16(v.y - __bfloat162float(hy));
            __nv_bfloat162 l1; l1.x = __float2bfloat16(v.z - __bfloat162float(hz));
                               l1.y = __float2bfloat16(v.w - __bfloat162float(hw));
            int so = r * ASTR + kq;
            *(__nv_bfloat162*)(Ah + so)     = h0;
            *(__nv_bfloat162*)(Ah + so + 2) = h1;
            *(__nv_bfloat162*)(Al + so)     = l0;
            *(__nv_bfloat162*)(Al + so + 2) = l1;
        }
        // ---- B chunk [64 x 64] bf16 hi/lo copy from gmem images
#pragma unroll
        for (int it = 0; it < 2; it++) {
            int i = tid + it * 256;
            int n = i >> 3, j = i & 7;
            uint4 vh = *((const uint4*)(g_wbh + n * 512 + c * 64) + j);
            uint4 vl = *((const uint4*)(g_wbl + n * 512 + c * 64) + j);
            *((uint4*)((char*)Bh + n * 144) + j) = vh;
            *((uint4*)((char*)Bl + n * 144) + j) = vl;
        }
        __syncthreads();

        // ---- compute: 4 k-steps; ldmatrix fragments; 3-term split mma
#pragma unroll
        for (int ks = 0; ks < 4; ks++) {
            uint32_t kadd = (uint32_t)(ks * 32);
            uint32_t ah[4], al[4];
            ldsm4(ah, sb + SM_AHI_O + a_off + kadd);
            ldsm4(al, sb + SM_ALO_O + a_off + kadd);
#pragma unroll
            for (int p = 0; p < 4; p++) {
                uint32_t boff = b_off_base + (uint32_t)(p * 16 * 144) + kadd;
                uint32_t bh[4], bl[4];
                ldsm4(bh, sb + SM_BHI_O + boff);
                ldsm4(bl, sb + SM_BLO_O + boff);
                mma_bf16(acc[2 * p],     ah, bh[0], bh[1]);
                mma_bf16(acc[2 * p],     al, bh[0], bh[1]);
                mma_bf16(acc[2 * p],     ah, bl[0], bl[1]);
                mma_bf16(acc[2 * p + 1], ah, bh[2], bh[3]);
                mma_bf16(acc[2 * p + 1], al, bh[2], bh[3]);
                mma_bf16(acc[2 * p + 1], ah, bl[2], bl[3]);
            }
        }
        __syncthreads();
    }

    // ---- epilogue: c0..c3 -> rows (gr, gr+8), cols (2t, 2t+1)
    int r1 = row0 + w * 16 + gr;
    int r2 = r1 + 8;
#pragma unroll
    for (int nt = 0; nt < 8; nt++) {
        int col = nt * 8 + t * 2;
        if (r1 < M) *(float2*)&C[(size_t)r1 * 64 + col] = make_float2(acc[nt][0], acc[nt][1]);
        if (r2 < M) *(float2*)&C[(size_t)r2 * 64 + col] = make_float2(acc[nt][2], acc[nt][3]);
    }
}

// ---------------- fp32 GEMM (round-6, conv1 K=64) --------------------------
__global__ void k_gemm128(const float* __restrict__ A, const float* __restrict__ B,
                          float* __restrict__ C, int M, int K) {
    __shared__ float As[16][128];
    __shared__ float Bs[16][64];
    int tid = threadIdx.x;
    int tx = tid & 15;
    int ty = tid >> 4;
    int row0 = blockIdx.x * 128;

    float acc[8][4] = {};

    for (int kt = 0; kt < K; kt += 16) {
#pragma unroll
        for (int j = 0; j < 2; j++) {
            int f4 = tid * 2 + j;
            int r = f4 >> 2;
            int kq = (f4 & 3) * 4;
            int row = row0 + r;
            float4 v = (row < M) ? *(const float4*)&A[(size_t)row * K + kt + kq]
                                 : make_float4(0.f, 0.f, 0.f, 0.f);
            As[kq + 0][r] = v.x;
            As[kq + 1][r] = v.y;
            As[kq + 2][r] = v.z;
            As[kq + 3][r] = v.w;
        }
        {
            int bk = tid >> 4, bc = (tid & 15) * 4;
            *(float4*)&Bs[bk][bc] = *(const float4*)&B[(size_t)(kt + bk) * 64 + bc];
        }
        __syncthreads();
#pragma unroll
        for (int kk = 0; kk < 16; kk++) {
            float4 a0 = *(const float4*)&As[kk][ty * 8];
            float4 a1 = *(const float4*)&As[kk][ty * 8 + 4];
            float4 b  = *(const float4*)&Bs[kk][tx * 4];
            float av[8] = {a0.x, a0.y, a0.z, a0.w, a1.x, a1.y, a1.z, a1.w};
            float bv[4] = {b.x, b.y, b.z, b.w};
#pragma unroll
            for (int i = 0; i < 8; i++)
#pragma unroll
                for (int j = 0; j < 4; j++)
                    acc[i][j] += av[i] * bv[j];
        }
        __syncthreads();
    }
#pragma unroll
    for (int i = 0; i < 8; i++) {
        int row = row0 + ty * 8 + i;
        if (row < M) {
            float4 v = make_float4(acc[i][0], acc[i][1], acc[i][2], acc[i][3]);
            *(float4*)&C[(size_t)row * 64 + tx * 4] = v;
        }
    }
}

// ---------------- CSR gather + self-loop + bias + SELU -> g_h (round-6) ----
__global__ void k_gather(const float* __restrict__ bias) {
    int t = blockIdx.x * blockDim.x + threadIdx.x;
    if (t >= NN * 16) return;
    int n = t >> 4;
    int q = (t & 15) << 2;

    float d = g_deg[n];
    float dd = d * d;
    float4 v = *(const float4*)&g_xw[(size_t)n * 64 + q];
    float4 acc = make_float4(v.x * dd, v.y * dd, v.z * dd, v.w * dd);

    int s = g_rowptr[n], e2 = g_rowptr[n + 1];
    int i = s;
    for (; i + 1 < e2; i += 2) {
        int s0 = g_csrc[i], s1 = g_csrc[i + 1];
        float n0 = g_cnrm[i], n1 = g_cnrm[i + 1];
        float4 u0 = *(const float4*)&g_xw[(size_t)s0 * 64 + q];
        float4 u1 = *(const float4*)&g_xw[(size_t)s1 * 64 + q];
        acc.x += n0 * u0.x + n1 * u1.x;
        acc.y += n0 * u0.y + n1 * u1.y;
        acc.z += n0 * u0.z + n1 * u1.z;
        acc.w += n0 * u0.w + n1 * u1.w;
    }
    if (i < e2) {
        int s0 = g_csrc[i];
        float n0 = g_cnrm[i];
        float4 u0 = *(const float4*)&g_xw[(size_t)s0 * 64 + q];
        acc.x += n0 * u0.x;
        acc.y += n0 * u0.y;
        acc.z += n0 * u0.z;
        acc.w += n0 * u0.w;
    }

    float4 b4 = *(const float4*)&bias[q];
    float4 o;
    o.x = selu_f(acc.x + b4.x);
    o.y = selu_f(acc.y + b4.y);
    o.z = selu_f(acc.z + b4.z);
    o.w = selu_f(acc.w + b4.w);
    *(float4*)&g_h[(size_t)n * 64 + q] = o;
}

// ---------------- fused dense MLP + softmax (round-6) ----------------------
__global__ void k_dense(const float* __restrict__ w0, const float* __restrict__ b0,
                        const float* __restrict__ w1, const float* __restrict__ b1,
                        const float* __restrict__ w2, const float* __restrict__ b2,
                        const float* __restrict__ w3, const float* __restrict__ b3,
                        float* __restrict__ out) {
    __shared__ float Ws[64][64];
    __shared__ float hs[16][64];
    __shared__ float lg[16][20];
    __shared__ float bs[64];

    int tid = threadIdx.x;
    int j = tid & 63, rq = tid >> 6;
    int row0 = blockIdx.x * 16;

    for (int i = tid; i < 16 * 64; i += 256) {
        int r = i >> 6, f = i & 63;
        int row = row0 + r;
        hs[r][f] = (row < NN) ? g_h[(size_t)row * 64 + f] : 0.f;
    }

    const float* Wp[3] = {w0, w1, w2};
    const float* Bp[3] = {b0, b1, b2};

    for (int L = 0; L < 3; L++) {
        __syncthreads();
        for (int i = tid; i < 4096; i += 256) Ws[i >> 6][i & 63] = Wp[L][i];
        if (tid < 64) bs[tid] = Bp[L][tid];
        __syncthreads();
        float acc[4];
#pragma unroll
        for (int i = 0; i < 4; i++) acc[i] = bs[j];
        for (int k = 0; k < 64; k++) {
            float wv = Ws[k][j];
#pragma unroll
            for (int i = 0; i < 4; i++) acc[i] += hs[rq * 4 + i][k] * wv;
        }
        __syncthreads();
#pragma unroll
        for (int i = 0; i < 4; i++) hs[rq * 4 + i][j] = selu_f(acc[i]);
    }

    __syncthreads();
    for (int i = tid; i < 64 * 20; i += 256) Ws[i / 20][i % 20] = w3[i];
    if (tid < 20) bs[tid] = b3[tid];
    __syncthreads();

    if (j < 20) {
        float acc[4];
#pragma unroll
        for (int i = 0; i < 4; i++) acc[i] = bs[j];
        for (int k = 0; k < 64; k++) {
            float wv = Ws[k][j];
#pragma unroll
            for (int i = 0; i < 4; i++) acc[i] += hs[rq * 4 + i][k] * wv;
        }
#pragma unroll
        for (int i = 0; i < 4; i++) lg[rq * 4 + i][j] = acc[i];
    }
    __syncthreads();

    for (int idx = tid; idx < 16 * 20; idx += 256) {
        int r = idx / 20, jj = idx % 20;
        int row = row0 + r;
        if (row < NN) {
            float mx = -1e30f;
#pragma unroll
            for (int k = 0; k < 20; k++) mx = fmaxf(mx, lg[r][k]);
            float s = 0.f;
#pragma unroll
            for (int k = 0; k < 20; k++) s += expf(lg[r][k] - mx);
            out[(size_t)row * 20 + jj] = expf(lg[r][jj] - mx) / s;
        }
    }
}

// ---------------- launch ----------------
extern "C" void kernel_launch(void* const* d_in, const int* in_sizes, int n_in,
                              void* d_out, int out_size) {
    const float* x    = (const float*)d_in[0];
    const int*   ei   = (const int*)d_in[1];      // int32 (JAX x64 disabled)
    const float* ea   = (const float*)d_in[2];
    const float* gc0w = (const float*)d_in[3];
    const float* gc0b = (const float*)d_in[4];
    const float* gc1w = (const float*)d_in[5];
    const float* gc1b = (const float*)d_in[6];
    const float* l0w  = (const float*)d_in[7];
    const float* l0b  = (const float*)d_in[8];
    const float* l1w  = (const float*)d_in[9];
    const float* l1b  = (const float*)d_in[10];
    const float* l2w  = (const float*)d_in[11];
    const float* l2b  = (const float*)d_in[12];
    const float* l3w  = (const float*)d_in[13];
    const float* l3b  = (const float*)d_in[14];
    float*       out  = (float*)d_out;

    float *xw, *h;
    cudaGetSymbolAddress((void**)&xw, g_xw);
    cudaGetSymbolAddress((void**)&h,  g_h);

    cudaFuncSetAttribute(k_conv0_mma, cudaFuncAttributeMaxDynamicSharedMemorySize, SM_MMA_TOT);

    const int T = 256;

    // normalization + CSR build + W split-bf16 images
    k_deg_init<<<(NN + T - 1) / T, T>>>();
    k_deg_acc<<<(EE + T - 1) / T, T>>>(ei, ea);
    k_scan1<<<NBLK, SCAN_BLK>>>();
    k_scan_top<<<1, 128>>>();
    k_scan_add<<<NBLK, SCAN_BLK>>>();
    k_fill<<<(EE + T - 1) / T, T>>>(ei, ea);
    k_wb<<<(512 * 64 + T - 1) / T, T>>>(gc0w);

    // conv 0: tensor-core (mma.sync bf16 split + ldmatrix) GEMM
    k_conv0_mma<<<(NN + 127) / 128, T, SM_MMA_TOT>>>(x, xw, NN);
    k_gather<<<(NN * 16 + T - 1) / T, T>>>(gc0b);

    // conv 1: fp32 GEMM (K=64)
    k_gemm128<<<(NN + 127) / 128, T>>>(h, gc1w, xw, NN, HGD);
    k_gather<<<(NN * 16 + T - 1) / T, T>>>(gc1b);

    // dense stack + softmax
    k_dense<<<(NN + 15) / 16, T>>>(l0w, l0b, l1w, l1b, l2w, l2b, l3w, l3b, out);
}

// round 12
// speedup vs baseline: 2.1529x; 1.3821x over previous
#include <cuda_runtime.h>
#include <cuda_bf16.h>
#include <math.h>
#include <stdint.h>

#define NN  100000
#define EE  1600000
#define IND 512
#define HGD 64
#define OUTD 20

#define SCAN_BLK 1024
#define NBLK ((NN + SCAN_BLK - 1) / SCAN_BLK)   // 98

typedef unsigned long long ull;

// ---------------- scratch (static device globals; no allocs) ----------------
__device__ __align__(8) float2 g_dc[NN];  // (deg, cnt) accumulated together
__device__ float g_deg[NN];               // dinv after scan_add
__device__ int   g_rowptr[NN + 1];
__device__ int   g_cursor[NN];
__device__ int   g_bsum[NBLK];
__device__ int   g_csrc[EE];
__device__ float g_cnrm[EE];
__device__ __align__(16) float g_xw[(size_t)NN * HGD];
__device__ __align__(16) float g_h[(size_t)NN * HGD];
// gc0_w split-bf16 images, [n][k] layout (n=0..63, k=0..511)
__device__ __align__(16) __nv_bfloat16 g_wbh[64 * 512];
__device__ __align__(16) __nv_bfloat16 g_wbl[64 * 512];
// dense weights split-bf16 images: [L][n][k], L=0..2 (64x64), W3 padded 32x64
__device__ __align__(16) __nv_bfloat16 g_wdh[3 * 64 * 64];
__device__ __align__(16) __nv_bfloat16 g_wdl[3 * 64 * 64];
__device__ __align__(16) __nv_bfloat16 g_w3h[32 * 64];
__device__ __align__(16) __nv_bfloat16 g_w3l[32 * 64];

__device__ __forceinline__ float selu_f(float x) {
    const float a = 1.6732632423543772f, s = 1.0507009873554805f;
    return s * (x > 0.f ? x : a * expm1f(x));
}

// warp-level bf16 MMA (sm_80+ PTX; valid on compute_103 baseline target)
__device__ __forceinline__ void mma_bf16(float* c, const uint32_t* a, uint32_t b0, uint32_t b1) {
    asm volatile(
        "mma.sync.aligned.m16n8k16.row.col.f32.bf16.bf16.f32 "
        "{%0,%1,%2,%3}, {%4,%5,%6,%7}, {%8,%9}, {%0,%1,%2,%3};"
        : "+f"(c[0]), "+f"(c[1]), "+f"(c[2]), "+f"(c[3])
        : "r"(a[0]), "r"(a[1]), "r"(a[2]), "r"(a[3]), "r"(b0), "r"(b1));
}

__device__ __forceinline__ void ldsm4(uint32_t* r, uint32_t addr) {
    asm volatile("ldmatrix.sync.aligned.m8n8.x4.shared.b16 {%0,%1,%2,%3}, [%4];"
                 : "=r"(r[0]), "=r"(r[1]), "=r"(r[2]), "=r"(r[3]) : "r"(addr));
}

__device__ __forceinline__ uint32_t smem_u32(const void* p) {
    uint32_t a;
    asm("{ .reg .u64 t; cvta.to.shared.u64 t, %1; cvt.u32.u64 %0, t; }" : "=r"(a) : "l"(p));
    return a;
}

// split f32 pair -> packed bf16x2 (hi, lo)
__device__ __forceinline__ void split2(float x, float y, uint32_t& hi, uint32_t& lo) {
    __nv_bfloat16 hx = __float2bfloat16(x), hy = __float2bfloat16(y);
    __nv_bfloat162 h; h.x = hx; h.y = hy;
    __nv_bfloat162 l; l.x = __float2bfloat16(x - __bfloat162float(hx));
                      l.y = __float2bfloat16(y - __bfloat162float(hy));
    hi = *(uint32_t*)&h;
    lo = *(uint32_t*)&l;
}

// ---------------- degree + count ----------------
__global__ void k_deg_init() {
    int i = blockIdx.x * blockDim.x + threadIdx.x;
    if (i < NN) g_dc[i] = make_float2(1.0f, 0.0f);   // self-loop weight 1
}

__global__ void k_deg_acc(const int* __restrict__ ei, const float* __restrict__ w) {
    int e = blockIdx.x * blockDim.x + threadIdx.x;
    if (e < EE) {
        int c = ei[EE + e];
        asm volatile("red.global.add.v2.f32 [%0], {%1, %2};"
                     :: "l"(&g_dc[c]), "f"(w[e]), "f"(1.0f) : "memory");
    }
}

// ---------------- exclusive scan over cnt -> g_rowptr ----------------
__global__ void k_scan1() {
    __shared__ int sh[SCAN_BLK];
    int i = blockIdx.x * SCAN_BLK + threadIdx.x;
    int v = (i < NN) ? (int)g_dc[i].y : 0;
    sh[threadIdx.x] = v;
    __syncthreads();
    for (int off = 1; off < SCAN_BLK; off <<= 1) {
        int t = (threadIdx.x >= off) ? sh[threadIdx.x - off] : 0;
        __syncthreads();
        sh[threadIdx.x] += t;
        __syncthreads();
    }
    if (i < NN) g_rowptr[i] = sh[threadIdx.x] - v;
    if (threadIdx.x == SCAN_BLK - 1) g_bsum[blockIdx.x] = sh[threadIdx.x];
}

__global__ void k_scan_top() {
    __shared__ int sh[128];
    int t = threadIdx.x;
    int v = (t < NBLK) ? g_bsum[t] : 0;
    sh[t] = v;
    __syncthreads();
    for (int off = 1; off < 128; off <<= 1) {
        int u = (t >= off) ? sh[t - off] : 0;
        __syncthreads();
        sh[t] += u;
        __syncthreads();
    }
    if (t < NBLK) g_bsum[t] = sh[t] - v;
}

__global__ void k_scan_add() {
    int i = blockIdx.x * SCAN_BLK + threadIdx.x;
    if (i < NN) {
        int r = g_rowptr[i] + g_bsum[blockIdx.x];
        g_rowptr[i] = r;
        g_cursor[i] = r;
        float d = g_dc[i].x;
        g_deg[i] = d > 0.f ? rsqrtf(fmaxf(d, 1e-30f)) : 0.f;
    }
    if (i == 0) g_rowptr[NN] = EE;
}

// ---------------- CSR fill ----------------
__global__ void k_fill(const int* __restrict__ ei, const float* __restrict__ w) {
    int e = blockIdx.x * blockDim.x + threadIdx.x;
    if (e < EE) {
        int r = ei[e];
        int c = ei[EE + e];
        int pos = atomicAdd(&g_cursor[c], 1);
        g_csrc[pos] = r;
        g_cnrm[pos] = g_deg[r] * w[e] * g_deg[c];
    }
}

// ---------------- gc0_w -> split-bf16 images, [n][k] ------------------------
__global__ void k_wb(const float* __restrict__ W) {
    int i = blockIdx.x * blockDim.x + threadIdx.x;
    if (i >= 512 * 64) return;
    int k = i >> 6, n = i & 63;
    float w = W[i];
    __nv_bfloat16 hi = __float2bfloat16(w);
    __nv_bfloat16 lo = __float2bfloat16(w - __bfloat162float(hi));
    g_wbh[n * 512 + k] = hi;
    g_wbl[n * 512 + k] = lo;
}

// ---------------- dense weights -> split-bf16 images ------------------------
__global__ void k_wd(const float* __restrict__ w0, const float* __restrict__ w1,
                     const float* __restrict__ w2, const float* __restrict__ w3) {
    int i = blockIdx.x * blockDim.x + threadIdx.x;
    if (i < 3 * 4096) {
        int L = i >> 12, r = i & 4095;
        int k = r >> 6, n = r & 63;
        const float* W = (L == 0) ? w0 : ((L == 1) ? w1 : w2);
        float v = W[k * 64 + n];
        __nv_bfloat16 hi = __float2bfloat16(v);
        __nv_bfloat16 lo = __float2bfloat16(v - __bfloat162float(hi));
        g_wdh[L * 4096 + n * 64 + k] = hi;
        g_wdl[L * 4096 + n * 64 + k] = lo;
    } else if (i < 3 * 4096 + 2048) {
        int r = i - 12288;
        int n = r >> 6, k = r & 63;
        float v = (n < 20) ? w3[k * 20 + n] : 0.f;
        __nv_bfloat16 hi = __float2bfloat16(v);
        __nv_bfloat16 lo = __float2bfloat16(v - __bfloat162float(hi));
        g_w3h[n * 64 + k] = hi;
        g_w3l[n * 64 + k] = lo;
    }
}

// ---------------- conv0 GEMM on mma.sync bf16, split-bf16, ldmatrix --------
#define ASTR 72
#define SM_AHI_O 0
#define SM_ALO_O 18432
#define SM_BHI_O 36864
#define SM_BLO_O 46080
#define SM_MMA_TOT 55296
__global__ void k_conv0_mma(const float* __restrict__ A, float* __restrict__ C, int M) {
    extern __shared__ __align__(16) char smem[];
    __nv_bfloat16* Ah = (__nv_bfloat16*)(smem + SM_AHI_O);
    __nv_bfloat16* Al = (__nv_bfloat16*)(smem + SM_ALO_O);
    __nv_bfloat16* Bh = (__nv_bfloat16*)(smem + SM_BHI_O);
    __nv_bfloat16* Bl = (__nv_bfloat16*)(smem + SM_BLO_O);

    int tid = threadIdx.x;
    int w = tid >> 5, lane = tid & 31;
    int gr = lane >> 2, t = lane & 3;
    int row0 = blockIdx.x * 128;
    uint32_t sb = smem_u32(smem);

    uint32_t a_off = (uint32_t)((w * 16 + (lane & 7) + ((lane >> 3) & 1) * 8) * 144
                                + ((lane >> 4) & 1) * 16);
    uint32_t b_off_base = (uint32_t)((((lane >> 4) & 1) * 8 + (lane & 7)) * 144
                                     + ((lane >> 3) & 1) * 16);

    float acc[8][4];
#pragma unroll
    for (int i = 0; i < 8; i++)
#pragma unroll
        for (int j = 0; j < 4; j++) acc[i][j] = 0.f;

    for (int c = 0; c < 8; c++) {
#pragma unroll
        for (int it = 0; it < 8; it++) {
            int idx = tid + it * 256;
            int r = idx >> 4;
            int kq = (idx & 15) * 4;
            int row = row0 + r;
            float4 v = (row < M) ? *(const float4*)&A[(size_t)row * 512 + c * 64 + kq]
                                 : make_float4(0.f, 0.f, 0.f, 0.f);
            uint32_t h0, l0, h1, l1;
            split2(v.x, v.y, h0, l0);
            split2(v.z, v.w, h1, l1);
            int so = r * ASTR + kq;
            *(uint32_t*)(Ah + so)     = h0;
            *(uint32_t*)(Ah + so + 2) = h1;
            *(uint32_t*)(Al + so)     = l0;
            *(uint32_t*)(Al + so + 2) = l1;
        }
#pragma unroll
        for (int it = 0; it < 2; it++) {
            int i = tid + it * 256;
            int n = i >> 3, j = i & 7;
            uint4 vh = *((const uint4*)(g_wbh + n * 512 + c * 64) + j);
            uint4 vl = *((const uint4*)(g_wbl + n * 512 + c * 64) + j);
            *((uint4*)((char*)Bh + n * 144) + j) = vh;
            *((uint4*)((char*)Bl + n * 144) + j) = vl;
        }
        __syncthreads();

#pragma unroll
        for (int ks = 0; ks < 4; ks++) {
            uint32_t kadd = (uint32_t)(ks * 32);
            uint32_t ah[4], al[4];
            ldsm4(ah, sb + SM_AHI_O + a_off + kadd);
            ldsm4(al, sb + SM_ALO_O + a_off + kadd);
#pragma unroll
            for (int p = 0; p < 4; p++) {
                uint32_t boff = b_off_base + (uint32_t)(p * 16 * 144) + kadd;
                uint32_t bh[4], bl[4];
                ldsm4(bh, sb + SM_BHI_O + boff);
                ldsm4(bl, sb + SM_BLO_O + boff);
                mma_bf16(acc[2 * p],     ah, bh[0], bh[1]);
                mma_bf16(acc[2 * p],     al, bh[0], bh[1]);
                mma_bf16(acc[2 * p],     ah, bl[0], bl[1]);
                mma_bf16(acc[2 * p + 1], ah, bh[2], bh[3]);
                mma_bf16(acc[2 * p + 1], al, bh[2], bh[3]);
                mma_bf16(acc[2 * p + 1], ah, bl[2], bl[3]);
            }
        }
        __syncthreads();
    }

    int r1 = row0 + w * 16 + gr;
    int r2 = r1 + 8;
#pragma unroll
    for (int nt = 0; nt < 8; nt++) {
        int col = nt * 8 + t * 2;
        if (r1 < M) *(float2*)&C[(size_t)r1 * 64 + col] = make_float2(acc[nt][0], acc[nt][1]);
        if (r2 < M) *(float2*)&C[(size_t)r2 * 64 + col] = make_float2(acc[nt][2], acc[nt][3]);
    }
}

// ---------------- fp32 GEMM (conv1, K=64) ----------------------------------
__global__ void k_gemm128(const float* __restrict__ A, const float* __restrict__ B,
                          float* __restrict__ C, int M, int K) {
    __shared__ float As[16][128];
    __shared__ float Bs[16][64];
    int tid = threadIdx.x;
    int tx = tid & 15;
    int ty = tid >> 4;
    int row0 = blockIdx.x * 128;

    float acc[8][4] = {};

    for (int kt = 0; kt < K; kt += 16) {
#pragma unroll
        for (int j = 0; j < 2; j++) {
            int f4 = tid * 2 + j;
            int r = f4 >> 2;
            int kq = (f4 & 3) * 4;
            int row = row0 + r;
            float4 v = (row < M) ? *(const float4*)&A[(size_t)row * K + kt + kq]
                                 : make_float4(0.f, 0.f, 0.f, 0.f);
            As[kq + 0][r] = v.x;
            As[kq + 1][r] = v.y;
            As[kq + 2][r] = v.z;
            As[kq + 3][r] = v.w;
        }
        {
            int bk = tid >> 4, bc = (tid & 15) * 4;
            *(float4*)&Bs[bk][bc] = *(const float4*)&B[(size_t)(kt + bk) * 64 + bc];
        }
        __syncthreads();
#pragma unroll
        for (int kk = 0; kk < 16; kk++) {
            float4 a0 = *(const float4*)&As[kk][ty * 8];
            float4 a1 = *(const float4*)&As[kk][ty * 8 + 4];
            float4 b  = *(const float4*)&Bs[kk][tx * 4];
            float av[8] = {a0.x, a0.y, a0.z, a0.w, a1.x, a1.y, a1.z, a1.w};
            float bv[4] = {b.x, b.y, b.z, b.w};
#pragma unroll
            for (int i = 0; i < 8; i++)
#pragma unroll
                for (int j = 0; j < 4; j++)
                    acc[i][j] += av[i] * bv[j];
        }
        __syncthreads();
    }
#pragma unroll
    for (int i = 0; i < 8; i++) {
        int row = row0 + ty * 8 + i;
        if (row < M) {
            float4 v = make_float4(acc[i][0], acc[i][1], acc[i][2], acc[i][3]);
            *(float4*)&C[(size_t)row * 64 + tx * 4] = v;
        }
    }
}

// ---------------- CSR gather + self-loop + bias + SELU -> g_h --------------
__global__ void k_gather(const float* __restrict__ bias) {
    int t = blockIdx.x * blockDim.x + threadIdx.x;
    if (t >= NN * 16) return;
    int n = t >> 4;
    int q = (t & 15) << 2;

    float d = g_deg[n];
    float dd = d * d;
    float4 v = *(const float4*)&g_xw[(size_t)n * 64 + q];
    float4 acc = make_float4(v.x * dd, v.y * dd, v.z * dd, v.w * dd);

    int s = g_rowptr[n], e2 = g_rowptr[n + 1];
    int i = s;
    for (; i + 1 < e2; i += 2) {
        int s0 = g_csrc[i], s1 = g_csrc[i + 1];
        float n0 = g_cnrm[i], n1 = g_cnrm[i + 1];
        float4 u0 = *(const float4*)&g_xw[(size_t)s0 * 64 + q];
        float4 u1 = *(const float4*)&g_xw[(size_t)s1 * 64 + q];
        acc.x += n0 * u0.x + n1 * u1.x;
        acc.y += n0 * u0.y + n1 * u1.y;
        acc.z += n0 * u0.z + n1 * u1.z;
        acc.w += n0 * u0.w + n1 * u1.w;
    }
    if (i < e2) {
        int s0 = g_csrc[i];
        float n0 = g_cnrm[i];
        float4 u0 = *(const float4*)&g_xw[(size_t)s0 * 64 + q];
        acc.x += n0 * u0.x;
        acc.y += n0 * u0.y;
        acc.z += n0 * u0.z;
        acc.w += n0 * u0.w;
    }

    float4 b4 = *(const float4*)&bias[q];
    float4 o;
    o.x = selu_f(acc.x + b4.x);
    o.y = selu_f(acc.y + b4.y);
    o.z = selu_f(acc.z + b4.z);
    o.w = selu_f(acc.w + b4.w);
    *(float4*)&g_h[(size_t)n * 64 + q] = o;
}

// ---------------- dense MLP on mma.sync: 3x(64x64)+SELU, 64x20, softmax ----
#define DM_AH 0
#define DM_AL 18432
#define DM_BH 36864
#define DM_BL 46080
#define DM_BS 55296
#define DM_TOT 55552
__global__ void k_dense_mma(const float* __restrict__ b0, const float* __restrict__ b1,
                            const float* __restrict__ b2, const float* __restrict__ b3,
                            float* __restrict__ out, int M) {
    extern __shared__ __align__(16) char smem[];
    __nv_bfloat16* Ah = (__nv_bfloat16*)(smem + DM_AH);
    __nv_bfloat16* Al = (__nv_bfloat16*)(smem + DM_AL);
    float* bs = (float*)(smem + DM_BS);

    int tid = threadIdx.x;
    int w = tid >> 5, lane = tid & 31;
    int gr = lane >> 2, t = lane & 3;
    int row0 = blockIdx.x * 128;
    uint32_t sb = smem_u32(smem);

    uint32_t a_off = (uint32_t)((w * 16 + (lane & 7) + ((lane >> 3) & 1) * 8) * 144
                                + ((lane >> 4) & 1) * 16);
    uint32_t b_off_base = (uint32_t)((((lane >> 4) & 1) * 8 + (lane & 7)) * 144
                                     + ((lane >> 3) & 1) * 16);

    // initial A: g_h -> split bf16 smem
#pragma unroll
    for (int it = 0; it < 8; it++) {
        int idx = tid + it * 256;          // 0..2047 float4s
        int r = idx >> 4;                  // 0..127
        int kq = (idx & 15) * 4;           // 0..60
        int row = row0 + r;
        float4 v = (row < M) ? *(const float4*)&g_h[(size_t)row * 64 + kq]
                             : make_float4(0.f, 0.f, 0.f, 0.f);
        uint32_t h0, l0, h1, l1;
        split2(v.x, v.y, h0, l0);
        split2(v.z, v.w, h1, l1);
        int so = r * ASTR + kq;
        *(uint32_t*)(Ah + so)     = h0;
        *(uint32_t*)(Ah + so + 2) = h1;
        *(uint32_t*)(Al + so)     = l0;
        *(uint32_t*)(Al + so + 2) = l1;
    }

    const float* Bp[3] = {b0, b1, b2};

    for (int L = 0; L < 3; L++) {
        // stage weight images (64 rows x 128B) + bias
#pragma unroll
        for (int it = 0; it < 2; it++) {
            int i = tid + it * 256;        // 0..511
            int n = i >> 3, j = i & 7;
            uint4 vh = *((const uint4*)(g_wdh + L * 4096 + n * 64) + j);
            uint4 vl = *((const uint4*)(g_wdl + L * 4096 + n * 64) + j);
            *((uint4*)(smem + DM_BH + n * 144) + j) = vh;
            *((uint4*)(smem + DM_BL + n * 144) + j) = vl;
        }
        if (tid < 64) bs[tid] = Bp[L][tid];
        __syncthreads();

        float acc[8][4];
#pragma unroll
        for (int i = 0; i < 8; i++)
#pragma unroll
            for (int j = 0; j < 4; j++) acc[i][j] = 0.f;

#pragma unroll
        for (int ks = 0; ks < 4; ks++) {
            uint32_t kadd = (uint32_t)(ks * 32);
            uint32_t ah[4], al[4];
            ldsm4(ah, sb + DM_AH + a_off + kadd);
            ldsm4(al, sb + DM_AL + a_off + kadd);
#pragma unroll
            for (int p = 0; p < 4; p++) {
                uint32_t boff = b_off_base + (uint32_t)(p * 16 * 144) + kadd;
                uint32_t bh[4], bl[4];
                ldsm4(bh, sb + DM_BH + boff);
                ldsm4(bl, sb + DM_BL + boff);
                mma_bf16(acc[2 * p],     ah, bh[0], bh[1]);
                mma_bf16(acc[2 * p],     al, bh[0], bh[1]);
                mma_bf16(acc[2 * p],     ah, bl[0], bl[1]);
                mma_bf16(acc[2 * p + 1], ah, bh[2], bh[3]);
                mma_bf16(acc[2 * p + 1], al, bh[2], bh[3]);
                mma_bf16(acc[2 * p + 1], ah, bl[2], bl[3]);
            }
        }

        // bias + SELU + re-split (registers), then write back after sync
        uint32_t whi[8][2], wlo[8][2];
#pragma unroll
        for (int nt = 0; nt < 8; nt++) {
            float2 bb = *(const float2*)&bs[nt * 8 + 2 * t];
            float c0 = selu_f(acc[nt][0] + bb.x);
            float c1 = selu_f(acc[nt][1] + bb.y);
            float c2 = selu_f(acc[nt][2] + bb.x);
            float c3 = selu_f(acc[nt][3] + bb.y);
            split2(c0, c1, whi[nt][0], wlo[nt][0]);
            split2(c2, c3, whi[nt][1], wlo[nt][1]);
        }
        __syncthreads();   // all ldmatrix reads of A done
        int ra = (w * 16 + gr) * ASTR;
        int rb = (w * 16 + gr + 8) * ASTR;
#pragma unroll
        for (int nt = 0; nt < 8; nt++) {
            int co = nt * 8 + 2 * t;
            *(uint32_t*)(Ah + ra + co) = whi[nt][0];
            *(uint32_t*)(Al + ra + co) = wlo[nt][0];
            *(uint32_t*)(Ah + rb + co) = whi[nt][1];
            *(uint32_t*)(Al + rb + co) = wlo[nt][1];
        }
        __syncthreads();
    }

    // final layer: W3 padded to 32 rows
    {
        int i = tid;                       // 0..255 covers 32 rows x 8 uint4
        int n = i >> 3, j = i & 7;
        uint4 vh = *((const uint4*)(g_w3h + n * 64) + j);
        uint4 vl = *((const uint4*)(g_w3l + n * 64) + j);
        *((uint4*)(smem + DM_BH + n * 144) + j) = vh;
        *((uint4*)(smem + DM_BL + n * 144) + j) = vl;
    }
    if (tid < 24) bs[tid] = (tid < 20) ? b3[tid] : 0.f;
    __syncthreads();

    float accf[4][4];
#pragma unroll
    for (int i = 0; i < 4; i++)
#pragma unroll
        for (int j = 0; j < 4; j++) accf[i][j] = 0.f;

#pragma unroll
    for (int ks = 0; ks < 4; ks++) {
        uint32_t kadd = (uint32_t)(ks * 32);
        uint32_t ah[4], al[4];
        ldsm4(ah, sb + DM_AH + a_off + kadd);
        ldsm4(al, sb + DM_AL + a_off + kadd);
#pragma unroll
        for (int p = 0; p < 2; p++) {
            uint32_t boff = b_off_base + (uint32_t)(p * 16 * 144) + kadd;
            uint32_t bh[4], bl[4];
            ldsm4(bh, sb + DM_BH + boff);
            ldsm4(bl, sb + DM_BL + boff);
            mma_bf16(accf[2 * p],     ah, bh[0], bh[1]);
            mma_bf16(accf[2 * p],     al, bh[0], bh[1]);
            mma_bf16(accf[2 * p],     ah, bl[0], bl[1]);
            mma_bf16(accf[2 * p + 1], ah, bh[2], bh[3]);
            mma_bf16(accf[2 * p + 1], al, bh[2], bh[3]);
            mma_bf16(accf[2 * p + 1], ah, bl[2], bl[3]);
        }
    }

    // logits: nt 0..2 hold cols nt*8+2t, +1 (cols >= 20 masked)
    float lg0[6], lg1[6];
#pragma unroll
    for (int nt = 0; nt < 3; nt++) {
        float2 bb = *(const float2*)&bs[nt * 8 + 2 * t];
        lg0[2 * nt]     = accf[nt][0] + bb.x;
        lg0[2 * nt + 1] = accf[nt][1] + bb.y;
        lg1[2 * nt]     = accf[nt][2] + bb.x;
        lg1[2 * nt + 1] = accf[nt][3] + bb.y;
    }
    bool v4 = (16 + 2 * t) < 20;           // nt2 pair validity (t<2)
    if (!v4) { lg0[4] = lg0[5] = lg1[4] = lg1[5] = -1e30f; }

    float m0 = lg0[0], m1 = lg1[0];
#pragma unroll
    for (int i = 1; i < 6; i++) { m0 = fmaxf(m0, lg0[i]); m1 = fmaxf(m1, lg1[i]); }
    m0 = fmaxf(m0, __shfl_xor_sync(0xffffffffu, m0, 1));
    m0 = fmaxf(m0, __shfl_xor_sync(0xffffffffu, m0, 2));
    m1 = fmaxf(m1, __shfl_xor_sync(0xffffffffu, m1, 1));
    m1 = fmaxf(m1, __shfl_xor_sync(0xffffffffu, m1, 2));

    float e0[6], e1[6], s0 = 0.f, s1 = 0.f;
#pragma unroll
    for (int i = 0; i < 6; i++) {
        e0[i] = expf(lg0[i] - m0);
        e1[i] = expf(lg1[i] - m1);
        s0 += e0[i];
        s1 += e1[i];
    }
    s0 += __shfl_xor_sync(0xffffffffu, s0, 1);
    s0 += __shfl_xor_sync(0xffffffffu, s0, 2);
    s1 += __shfl_xor_sync(0xffffffffu, s1, 1);
    s1 += __shfl_xor_sync(0xffffffffu, s1, 2);
    float i0 = 1.f / s0, i1 = 1.f / s1;

    int r1 = row0 + w * 16 + gr;
    int r2 = r1 + 8;
#pragma unroll
    for (int nt = 0; nt < 3; nt++) {
        if (nt == 2 && !v4) continue;
        int col = nt * 8 + 2 * t;
        if (r1 < M) *(float2*)&out[(size_t)r1 * 20 + col] = make_float2(e0[2 * nt] * i0, e0[2 * nt + 1] * i0);
        if (r2 < M) *(float2*)&out[(size_t)r2 * 20 + col] = make_float2(e1[2 * nt] * i1, e1[2 * nt + 1] * i1);
    }
}

// ---------------- launch ----------------
extern "C" void kernel_launch(void* const* d_in, const int* in_sizes, int n_in,
                              void* d_out, int out_size) {
    const float* x    = (const float*)d_in[0];
    const int*   ei   = (const int*)d_in[1];      // int32 (JAX x64 disabled)
    const float* ea   = (const float*)d_in[2];
    const float* gc0w = (const float*)d_in[3];
    const float* gc0b = (const float*)d_in[4];
    const float* gc1w = (const float*)d_in[5];
    const float* gc1b = (const float*)d_in[6];
    const float* l0w  = (const float*)d_in[7];
    const float* l0b  = (const float*)d_in[8];
    const float* l1w  = (const float*)d_in[9];
    const float* l1b  = (const float*)d_in[10];
    const float* l2w  = (const float*)d_in[11];
    const float* l2b  = (const float*)d_in[12];
    const float* l3w  = (const float*)d_in[13];
    const float* l3b  = (const float*)d_in[14];
    float*       out  = (float*)d_out;

    float *xw, *h;
    cudaGetSymbolAddress((void**)&xw, g_xw);
    cudaGetSymbolAddress((void**)&h,  g_h);

    cudaFuncSetAttribute(k_conv0_mma, cudaFuncAttributeMaxDynamicSharedMemorySize, SM_MMA_TOT);
    cudaFuncSetAttribute(k_dense_mma, cudaFuncAttributeMaxDynamicSharedMemorySize, DM_TOT);

    const int T = 256;

    // normalization + CSR build + weight images
    k_deg_init<<<(NN + T - 1) / T, T>>>();
    k_deg_acc<<<(EE + T - 1) / T, T>>>(ei, ea);
    k_scan1<<<NBLK, SCAN_BLK>>>();
    k_scan_top<<<1, 128>>>();
    k_scan_add<<<NBLK, SCAN_BLK>>>();
    k_fill<<<(EE + T - 1) / T, T>>>(ei, ea);
    k_wb<<<(512 * 64 + T - 1) / T, T>>>(gc0w);
    k_wd<<<(14336 + T - 1) / T, T>>>(l0w, l1w, l2w, l3w);

    // conv 0: tensor-core GEMM
    k_conv0_mma<<<(NN + 127) / 128, T, SM_MMA_TOT>>>(x, xw, NN);
    k_gather<<<(NN * 16 + T - 1) / T, T>>>(gc0b);

    // conv 1: fp32 GEMM (K=64)
    k_gemm128<<<(NN + 127) / 128, T>>>(h, gc1w, xw, NN, HGD);
    k_gather<<<(NN * 16 + T - 1) / T, T>>>(gc1b);

    // dense stack + softmax on tensor cores
    k_dense_mma<<<(NN + 127) / 128, T, DM_TOT>>>(l0b, l1b, l2b, l3b, out, NN);
}

// round 13
// speedup vs baseline: 2.3123x; 1.0740x over previous
#include <cuda_runtime.h>
#include <cuda_bf16.h>
#include <math.h>
#include <stdint.h>

#define NN  100000
#define EE  1600000
#define IND 512
#define HGD 64
#define OUTD 20

#define SCAN_BLK 1024
#define NBLK ((NN + SCAN_BLK - 1) / SCAN_BLK)   // 98

typedef unsigned long long ull;

// ---------------- scratch (static device globals; no allocs) ----------------
__device__ __align__(8) float2 g_dc[NN];  // (deg, cnt) accumulated together
__device__ float g_deg[NN];               // dinv after scan_add
__device__ int   g_rowptr[NN + 1];
__device__ int   g_cursor[NN];
__device__ int   g_bsum[NBLK];
__device__ __align__(8) int2 g_ce[EE];    // CSR: (src, norm-bits) packed
__device__ __align__(16) float g_xw[(size_t)NN * HGD];
__device__ __align__(16) float g_h[(size_t)NN * HGD];
// conv weights split-bf16 images, [n][k] layout
__device__ __align__(16) __nv_bfloat16 g_wbh[64 * 512];   // gc0_w
__device__ __align__(16) __nv_bfloat16 g_wbl[64 * 512];
__device__ __align__(16) __nv_bfloat16 g_w1h[64 * 64];    // gc1_w
__device__ __align__(16) __nv_bfloat16 g_w1l[64 * 64];
// dense weights split-bf16 images: [L][n][k], L=0..2 (64x64), W3 padded 32x64
__device__ __align__(16) __nv_bfloat16 g_wdh[3 * 64 * 64];
__device__ __align__(16) __nv_bfloat16 g_wdl[3 * 64 * 64];
__device__ __align__(16) __nv_bfloat16 g_w3h[32 * 64];
__device__ __align__(16) __nv_bfloat16 g_w3l[32 * 64];

__device__ __forceinline__ float selu_f(float x) {
    const float a = 1.6732632423543772f, s = 1.0507009873554805f;
    return s * (x > 0.f ? x : a * expm1f(x));
}

// warp-level bf16 MMA (sm_80+ PTX)
__device__ __forceinline__ void mma_bf16(float* c, const uint32_t* a, uint32_t b0, uint32_t b1) {
    asm volatile(
        "mma.sync.aligned.m16n8k16.row.col.f32.bf16.bf16.f32 "
        "{%0,%1,%2,%3}, {%4,%5,%6,%7}, {%8,%9}, {%0,%1,%2,%3};"
        : "+f"(c[0]), "+f"(c[1]), "+f"(c[2]), "+f"(c[3])
        : "r"(a[0]), "r"(a[1]), "r"(a[2]), "r"(a[3]), "r"(b0), "r"(b1));
}

__device__ __forceinline__ void ldsm4(uint32_t* r, uint32_t addr) {
    asm volatile("ldmatrix.sync.aligned.m8n8.x4.shared.b16 {%0,%1,%2,%3}, [%4];"
                 : "=r"(r[0]), "=r"(r[1]), "=r"(r[2]), "=r"(r[3]) : "r"(addr));
}

__device__ __forceinline__ uint32_t smem_u32(const void* p) {
    uint32_t a;
    asm("{ .reg .u64 t; cvta.to.shared.u64 t, %1; cvt.u32.u64 %0, t; }" : "=r"(a) : "l"(p));
    return a;
}

// split f32 pair -> packed bf16x2 (hi, lo)
__device__ __forceinline__ void split2(float x, float y, uint32_t& hi, uint32_t& lo) {
    __nv_bfloat16 hx = __float2bfloat16(x), hy = __float2bfloat16(y);
    __nv_bfloat162 h; h.x = hx; h.y = hy;
    __nv_bfloat162 l; l.x = __float2bfloat16(x - __bfloat162float(hx));
                      l.y = __float2bfloat16(y - __bfloat162float(hy));
    hi = *(uint32_t*)&h;
    lo = *(uint32_t*)&l;
}

// ---------------- degree + count ----------------
__global__ void k_deg_init() {
    int i = blockIdx.x * blockDim.x + threadIdx.x;
    if (i < NN) g_dc[i] = make_float2(1.0f, 0.0f);   // self-loop weight 1
}

__global__ void k_deg_acc(const int* __restrict__ ei, const float* __restrict__ w) {
    int e = blockIdx.x * blockDim.x + threadIdx.x;
    if (e < EE) {
        int c = ei[EE + e];
        asm volatile("red.global.add.v2.f32 [%0], {%1, %2};"
                     :: "l"(&g_dc[c]), "f"(w[e]), "f"(1.0f) : "memory");
    }
}

// ---------------- exclusive scan over cnt -> g_rowptr ----------------
__global__ void k_scan1() {
    __shared__ int sh[SCAN_BLK];
    int i = blockIdx.x * SCAN_BLK + threadIdx.x;
    int v = (i < NN) ? (int)g_dc[i].y : 0;
    sh[threadIdx.x] = v;
    __syncthreads();
    for (int off = 1; off < SCAN_BLK; off <<= 1) {
        int t = (threadIdx.x >= off) ? sh[threadIdx.x - off] : 0;
        __syncthreads();
        sh[threadIdx.x] += t;
        __syncthreads();
    }
    if (i < NN) g_rowptr[i] = sh[threadIdx.x] - v;
    if (threadIdx.x == SCAN_BLK - 1) g_bsum[blockIdx.x] = sh[threadIdx.x];
}

__global__ void k_scan_top() {
    __shared__ int sh[128];
    int t = threadIdx.x;
    int v = (t < NBLK) ? g_bsum[t] : 0;
    sh[t] = v;
    __syncthreads();
    for (int off = 1; off < 128; off <<= 1) {
        int u = (t >= off) ? sh[t - off] : 0;
        __syncthreads();
        sh[t] += u;
        __syncthreads();
    }
    if (t < NBLK) g_bsum[t] = sh[t] - v;
}

__global__ void k_scan_add() {
    int i = blockIdx.x * SCAN_BLK + threadIdx.x;
    if (i < NN) {
        int r = g_rowptr[i] + g_bsum[blockIdx.x];
        g_rowptr[i] = r;
        g_cursor[i] = r;
        float d = g_dc[i].x;
        g_deg[i] = d > 0.f ? rsqrtf(fmaxf(d, 1e-30f)) : 0.f;
    }
    if (i == 0) g_rowptr[NN] = EE;
}

// ---------------- CSR fill (packed int2) ----------------
__global__ void k_fill(const int* __restrict__ ei, const float* __restrict__ w) {
    int e = blockIdx.x * blockDim.x + threadIdx.x;
    if (e < EE) {
        int r = ei[e];
        int c = ei[EE + e];
        int pos = atomicAdd(&g_cursor[c], 1);
        float nm = g_deg[r] * w[e] * g_deg[c];
        g_ce[pos] = make_int2(r, __float_as_int(nm));
    }
}

// ---------------- conv weights -> split-bf16 images, [n][k] -----------------
__global__ void k_wb(const float* __restrict__ W0, const float* __restrict__ W1) {
    int i = blockIdx.x * blockDim.x + threadIdx.x;
    if (i < 512 * 64) {
        int k = i >> 6, n = i & 63;
        float w = W0[i];
        __nv_bfloat16 hi = __float2bfloat16(w);
        __nv_bfloat16 lo = __float2bfloat16(w - __bfloat162float(hi));
        g_wbh[n * 512 + k] = hi;
        g_wbl[n * 512 + k] = lo;
    } else if (i < 512 * 64 + 64 * 64) {
        int r = i - 512 * 64;
        int k = r >> 6, n = r & 63;
        float w = W1[r];
        __nv_bfloat16 hi = __float2bfloat16(w);
        __nv_bfloat16 lo = __float2bfloat16(w - __bfloat162float(hi));
        g_w1h[n * 64 + k] = hi;
        g_w1l[n * 64 + k] = lo;
    }
}

// ---------------- dense weights -> split-bf16 images ------------------------
__global__ void k_wd(const float* __restrict__ w0, const float* __restrict__ w1,
                     const float* __restrict__ w2, const float* __restrict__ w3) {
    int i = blockIdx.x * blockDim.x + threadIdx.x;
    if (i < 3 * 4096) {
        int L = i >> 12, r = i & 4095;
        int k = r >> 6, n = r & 63;
        const float* W = (L == 0) ? w0 : ((L == 1) ? w1 : w2);
        float v = W[k * 64 + n];
        __nv_bfloat16 hi = __float2bfloat16(v);
        __nv_bfloat16 lo = __float2bfloat16(v - __bfloat162float(hi));
        g_wdh[L * 4096 + n * 64 + k] = hi;
        g_wdl[L * 4096 + n * 64 + k] = lo;
    } else if (i < 3 * 4096 + 2048) {
        int r = i - 12288;
        int n = r >> 6, k = r & 63;
        float v = (n < 20) ? w3[k * 20 + n] : 0.f;
        __nv_bfloat16 hi = __float2bfloat16(v);
        __nv_bfloat16 lo = __float2bfloat16(v - __bfloat162float(hi));
        g_w3h[n * 64 + k] = hi;
        g_w3l[n * 64 + k] = lo;
    }
}

// ---------------- generic conv GEMM on mma.sync (split-bf16, ldmatrix) -----
// C[M,64] = A[M,K] @ W, K in {512, 64}; W given as [n][k] hi/lo images.
#define ASTR 72
#define SM_AHI_O 0
#define SM_ALO_O 18432
#define SM_BHI_O 36864
#define SM_BLO_O 46080
#define SM_MMA_TOT 55296
__global__ void k_conv_mma(const float* __restrict__ A, float* __restrict__ C, int M, int K,
                           const __nv_bfloat16* __restrict__ WH,
                           const __nv_bfloat16* __restrict__ WL) {
    extern __shared__ __align__(16) char smem[];
    __nv_bfloat16* Ah = (__nv_bfloat16*)(smem + SM_AHI_O);
    __nv_bfloat16* Al = (__nv_bfloat16*)(smem + SM_ALO_O);
    __nv_bfloat16* Bh = (__nv_bfloat16*)(smem + SM_BHI_O);
    __nv_bfloat16* Bl = (__nv_bfloat16*)(smem + SM_BLO_O);

    int tid = threadIdx.x;
    int w = tid >> 5, lane = tid & 31;
    int gr = lane >> 2, t = lane & 3;
    int row0 = blockIdx.x * 128;
    uint32_t sb = smem_u32(smem);

    uint32_t a_off = (uint32_t)((w * 16 + (lane & 7) + ((lane >> 3) & 1) * 8) * 144
                                + ((lane >> 4) & 1) * 16);
    uint32_t b_off_base = (uint32_t)((((lane >> 4) & 1) * 8 + (lane & 7)) * 144
                                     + ((lane >> 3) & 1) * 16);

    float acc[8][4];
#pragma unroll
    for (int i = 0; i < 8; i++)
#pragma unroll
        for (int j = 0; j < 4; j++) acc[i][j] = 0.f;

    int chunks = K >> 6;
    for (int c = 0; c < chunks; c++) {
#pragma unroll
        for (int it = 0; it < 8; it++) {
            int idx = tid + it * 256;
            int r = idx >> 4;
            int kq = (idx & 15) * 4;
            int row = row0 + r;
            float4 v = (row < M) ? *(const float4*)&A[(size_t)row * K + c * 64 + kq]
                                 : make_float4(0.f, 0.f, 0.f, 0.f);
            uint32_t h0, l0, h1, l1;
            split2(v.x, v.y, h0, l0);
            split2(v.z, v.w, h1, l1);
            int so = r * ASTR + kq;
            *(uint32_t*)(Ah + so)     = h0;
            *(uint32_t*)(Ah + so + 2) = h1;
            *(uint32_t*)(Al + so)     = l0;
            *(uint32_t*)(Al + so + 2) = l1;
        }
#pragma unroll
        for (int it = 0; it < 2; it++) {
            int i = tid + it * 256;
            int n = i >> 3, j = i & 7;
            uint4 vh = *((const uint4*)(WH + (size_t)n * K + c * 64) + j);
            uint4 vl = *((const uint4*)(WL + (size_t)n * K + c * 64) + j);
            *((uint4*)((char*)Bh + n * 144) + j) = vh;
            *((uint4*)((char*)Bl + n * 144) + j) = vl;
        }
        __syncthreads();

#pragma unroll
        for (int ks = 0; ks < 4; ks++) {
            uint32_t kadd = (uint32_t)(ks * 32);
            uint32_t ah[4], al[4];
            ldsm4(ah, sb + SM_AHI_O + a_off + kadd);
            ldsm4(al, sb + SM_ALO_O + a_off + kadd);
#pragma unroll
            for (int p = 0; p < 4; p++) {
                uint32_t boff = b_off_base + (uint32_t)(p * 16 * 144) + kadd;
                uint32_t bh[4], bl[4];
                ldsm4(bh, sb + SM_BHI_O + boff);
                ldsm4(bl, sb + SM_BLO_O + boff);
                mma_bf16(acc[2 * p],     ah, bh[0], bh[1]);
                mma_bf16(acc[2 * p],     al, bh[0], bh[1]);
                mma_bf16(acc[2 * p],     ah, bl[0], bl[1]);
                mma_bf16(acc[2 * p + 1], ah, bh[2], bh[3]);
                mma_bf16(acc[2 * p + 1], al, bh[2], bh[3]);
                mma_bf16(acc[2 * p + 1], ah, bl[2], bl[3]);
            }
        }
        __syncthreads();
    }

    int r1 = row0 + w * 16 + gr;
    int r2 = r1 + 8;
#pragma unroll
    for (int nt = 0; nt < 8; nt++) {
        int col = nt * 8 + t * 2;
        if (r1 < M) *(float2*)&C[(size_t)r1 * 64 + col] = make_float2(acc[nt][0], acc[nt][1]);
        if (r2 < M) *(float2*)&C[(size_t)r2 * 64 + col] = make_float2(acc[nt][2], acc[nt][3]);
    }
}

// ---------------- CSR gather + self-loop + bias + SELU -> g_h --------------
__global__ void k_gather(const float* __restrict__ bias) {
    int t = blockIdx.x * blockDim.x + threadIdx.x;
    if (t >= NN * 16) return;
    int n = t >> 4;
    int q = (t & 15) << 2;

    float d = g_deg[n];
    float dd = d * d;
    float4 v = *(const float4*)&g_xw[(size_t)n * 64 + q];
    float4 acc = make_float4(v.x * dd, v.y * dd, v.z * dd, v.w * dd);

    int s = g_rowptr[n], e2 = g_rowptr[n + 1];
    int i = s;
    for (; i + 1 < e2; i += 2) {
        int2 p0 = g_ce[i];
        int2 p1 = g_ce[i + 1];
        float n0 = __int_as_float(p0.y), n1 = __int_as_float(p1.y);
        float4 u0 = *(const float4*)&g_xw[(size_t)p0.x * 64 + q];
        float4 u1 = *(const float4*)&g_xw[(size_t)p1.x * 64 + q];
        acc.x += n0 * u0.x + n1 * u1.x;
        acc.y += n0 * u0.y + n1 * u1.y;
        acc.z += n0 * u0.z + n1 * u1.z;
        acc.w += n0 * u0.w + n1 * u1.w;
    }
    if (i < e2) {
        int2 p0 = g_ce[i];
        float n0 = __int_as_float(p0.y);
        float4 u0 = *(const float4*)&g_xw[(size_t)p0.x * 64 + q];
        acc.x += n0 * u0.x;
        acc.y += n0 * u0.y;
        acc.z += n0 * u0.z;
        acc.w += n0 * u0.w;
    }

    float4 b4 = *(const float4*)&bias[q];
    float4 o;
    o.x = selu_f(acc.x + b4.x);
    o.y = selu_f(acc.y + b4.y);
    o.z = selu_f(acc.z + b4.z);
    o.w = selu_f(acc.w + b4.w);
    *(float4*)&g_h[(size_t)n * 64 + q] = o;
}

// ---------------- dense MLP on mma.sync: 3x(64x64)+SELU, 64x20, softmax ----
#define DM_AH 0
#define DM_AL 18432
#define DM_BH 36864
#define DM_BL 46080
#define DM_BS 55296
#define DM_TOT 55552
__global__ void k_dense_mma(const float* __restrict__ b0, const float* __restrict__ b1,
                            const float* __restrict__ b2, const float* __restrict__ b3,
                            float* __restrict__ out, int M) {
    extern __shared__ __align__(16) char smem[];
    __nv_bfloat16* Ah = (__nv_bfloat16*)(smem + DM_AH);
    __nv_bfloat16* Al = (__nv_bfloat16*)(smem + DM_AL);
    float* bs = (float*)(smem + DM_BS);

    int tid = threadIdx.x;
    int w = tid >> 5, lane = tid & 31;
    int gr = lane >> 2, t = lane & 3;
    int row0 = blockIdx.x * 128;
    uint32_t sb = smem_u32(smem);

    uint32_t a_off = (uint32_t)((w * 16 + (lane & 7) + ((lane >> 3) & 1) * 8) * 144
                                + ((lane >> 4) & 1) * 16);
    uint32_t b_off_base = (uint32_t)((((lane >> 4) & 1) * 8 + (lane & 7)) * 144
                                     + ((lane >> 3) & 1) * 16);

    // initial A: g_h -> split bf16 smem
#pragma unroll
    for (int it = 0; it < 8; it++) {
        int idx = tid + it * 256;
        int r = idx >> 4;
        int kq = (idx & 15) * 4;
        int row = row0 + r;
        float4 v = (row < M) ? *(const float4*)&g_h[(size_t)row * 64 + kq]
                             : make_float4(0.f, 0.f, 0.f, 0.f);
        uint32_t h0, l0, h1, l1;
        split2(v.x, v.y, h0, l0);
        split2(v.z, v.w, h1, l1);
        int so = r * ASTR + kq;
        *(uint32_t*)(Ah + so)     = h0;
        *(uint32_t*)(Ah + so + 2) = h1;
        *(uint32_t*)(Al + so)     = l0;
        *(uint32_t*)(Al + so + 2) = l1;
    }

    const float* Bp[3] = {b0, b1, b2};

    for (int L = 0; L < 3; L++) {
#pragma unroll
        for (int it = 0; it < 2; it++) {
            int i = tid + it * 256;
            int n = i >> 3, j = i & 7;
            uint4 vh = *((const uint4*)(g_wdh + L * 4096 + n * 64) + j);
            uint4 vl = *((const uint4*)(g_wdl + L * 4096 + n * 64) + j);
            *((uint4*)(smem + DM_BH + n * 144) + j) = vh;
            *((uint4*)(smem + DM_BL + n * 144) + j) = vl;
        }
        if (tid < 64) bs[tid] = Bp[L][tid];
        __syncthreads();

        float acc[8][4];
#pragma unroll
        for (int i = 0; i < 8; i++)
#pragma unroll
            for (int j = 0; j < 4; j++) acc[i][j] = 0.f;

#pragma unroll
        for (int ks = 0; ks < 4; ks++) {
            uint32_t kadd = (uint32_t)(ks * 32);
            uint32_t ah[4], al[4];
            ldsm4(ah, sb + DM_AH + a_off + kadd);
            ldsm4(al, sb + DM_AL + a_off + kadd);
#pragma unroll
            for (int p = 0; p < 4; p++) {
                uint32_t boff = b_off_base + (uint32_t)(p * 16 * 144) + kadd;
                uint32_t bh[4], bl[4];
                ldsm4(bh, sb + DM_BH + boff);
                ldsm4(bl, sb + DM_BL + boff);
                mma_bf16(acc[2 * p],     ah, bh[0], bh[1]);
                mma_bf16(acc[2 * p],     al, bh[0], bh[1]);
                mma_bf16(acc[2 * p],     ah, bl[0], bl[1]);
                mma_bf16(acc[2 * p + 1], ah, bh[2], bh[3]);
                mma_bf16(acc[2 * p + 1], al, bh[2], bh[3]);
                mma_bf16(acc[2 * p + 1], ah, bl[2], bl[3]);
            }
        }

        uint32_t whi[8][2], wlo[8][2];
#pragma unroll
        for (int nt = 0; nt < 8; nt++) {
            float2 bb = *(const float2*)&bs[nt * 8 + 2 * t];
            float c0 = selu_f(acc[nt][0] + bb.x);
            float c1 = selu_f(acc[nt][1] + bb.y);
            float c2 = selu_f(acc[nt][2] + bb.x);
            float c3 = selu_f(acc[nt][3] + bb.y);
            split2(c0, c1, whi[nt][0], wlo[nt][0]);
            split2(c2, c3, whi[nt][1], wlo[nt][1]);
        }
        __syncthreads();
        int ra = (w * 16 + gr) * ASTR;
        int rb = (w * 16 + gr + 8) * ASTR;
#pragma unroll
        for (int nt = 0; nt < 8; nt++) {
            int co = nt * 8 + 2 * t;
            *(uint32_t*)(Ah + ra + co) = whi[nt][0];
            *(uint32_t*)(Al + ra + co) = wlo[nt][0];
            *(uint32_t*)(Ah + rb + co) = whi[nt][1];
            *(uint32_t*)(Al + rb + co) = wlo[nt][1];
        }
        __syncthreads();
    }

    // final layer: W3 padded to 32 rows
    {
        int i = tid;
        int n = i >> 3, j = i & 7;
        uint4 vh = *((const uint4*)(g_w3h + n * 64) + j);
        uint4 vl = *((const uint4*)(g_w3l + n * 64) + j);
        *((uint4*)(smem + DM_BH + n * 144) + j) = vh;
        *((uint4*)(smem + DM_BL + n * 144) + j) = vl;
    }
    if (tid < 24) bs[tid] = (tid < 20) ? b3[tid] : 0.f;
    __syncthreads();

    float accf[4][4];
#pragma unroll
    for (int i = 0; i < 4; i++)
#pragma unroll
        for (int j = 0; j < 4; j++) accf[i][j] = 0.f;

#pragma unroll
    for (int ks = 0; ks < 4; ks++) {
        uint32_t kadd = (uint32_t)(ks * 32);
        uint32_t ah[4], al[4];
        ldsm4(ah, sb + DM_AH + a_off + kadd);
        ldsm4(al, sb + DM_AL + a_off + kadd);
#pragma unroll
        for (int p = 0; p < 2; p++) {
            uint32_t boff = b_off_base + (uint32_t)(p * 16 * 144) + kadd;
            uint32_t bh[4], bl[4];
            ldsm4(bh, sb + DM_BH + boff);
            ldsm4(bl, sb + DM_BL + boff);
            mma_bf16(accf[2 * p],     ah, bh[0], bh[1]);
            mma_bf16(accf[2 * p],     al, bh[0], bh[1]);
            mma_bf16(accf[2 * p],     ah, bl[0], bl[1]);
            mma_bf16(accf[2 * p + 1], ah, bh[2], bh[3]);
            mma_bf16(accf[2 * p + 1], al, bh[2], bh[3]);
            mma_bf16(accf[2 * p + 1], ah, bl[2], bl[3]);
        }
    }

    float lg0[6], lg1[6];
#pragma unroll
    for (int nt = 0; nt < 3; nt++) {
        float2 bb = *(const float2*)&bs[nt * 8 + 2 * t];
        lg0[2 * nt]     = accf[nt][0] + bb.x;
        lg0[2 * nt + 1] = accf[nt][1] + bb.y;
        lg1[2 * nt]     = accf[nt][2] + bb.x;
        lg1[2 * nt + 1] = accf[nt][3] + bb.y;
    }
    bool v4 = (16 + 2 * t) < 20;
    if (!v4) { lg0[4] = lg0[5] = lg1[4] = lg1[5] = -1e30f; }

    float m0 = lg0[0], m1 = lg1[0];
#pragma unroll
    for (int i = 1; i < 6; i++) { m0 = fmaxf(m0, lg0[i]); m1 = fmaxf(m1, lg1[i]); }
    m0 = fmaxf(m0, __shfl_xor_sync(0xffffffffu, m0, 1));
    m0 = fmaxf(m0, __shfl_xor_sync(0xffffffffu, m0, 2));
    m1 = fmaxf(m1, __shfl_xor_sync(0xffffffffu, m1, 1));
    m1 = fmaxf(m1, __shfl_xor_sync(0xffffffffu, m1, 2));

    float e0[6], e1[6], s0 = 0.f, s1 = 0.f;
#pragma unroll
    for (int i = 0; i < 6; i++) {
        e0[i] = expf(lg0[i] - m0);
        e1[i] = expf(lg1[i] - m1);
        s0 += e0[i];
        s1 += e1[i];
    }
    s0 += __shfl_xor_sync(0xffffffffu, s0, 1);
    s0 += __shfl_xor_sync(0xffffffffu, s0, 2);
    s1 += __shfl_xor_sync(0xffffffffu, s1, 1);
    s1 += __shfl_xor_sync(0xffffffffu, s1, 2);
    float i0 = 1.f / s0, i1 = 1.f / s1;

    int r1 = row0 + w * 16 + gr;
    int r2 = r1 + 8;
#pragma unroll
    for (int nt = 0; nt < 3; nt++) {
        if (nt == 2 && !v4) continue;
        int col = nt * 8 + 2 * t;
        if (r1 < M) *(float2*)&out[(size_t)r1 * 20 + col] = make_float2(e0[2 * nt] * i0, e0[2 * nt + 1] * i0);
        if (r2 < M) *(float2*)&out[(size_t)r2 * 20 + col] = make_float2(e1[2 * nt] * i1, e1[2 * nt + 1] * i1);
    }
}

// ---------------- launch ----------------
extern "C" void kernel_launch(void* const* d_in, const int* in_sizes, int n_in,
                              void* d_out, int out_size) {
    const float* x    = (const float*)d_in[0];
    const int*   ei   = (const int*)d_in[1];      // int32 (JAX x64 disabled)
    const float* ea   = (const float*)d_in[2];
    const float* gc0w = (const float*)d_in[3];
    const float* gc0b = (const float*)d_in[4];
    const float* gc1w = (const float*)d_in[5];
    const float* gc1b = (const float*)d_in[6];
    const float* l0w  = (const float*)d_in[7];
    const float* l0b  = (const float*)d_in[8];
    const float* l1w  = (const float*)d_in[9];
    const float* l1b  = (const float*)d_in[10];
    const float* l2w  = (const float*)d_in[11];
    const float* l2b  = (const float*)d_in[12];
    const float* l3w  = (const float*)d_in[13];
    const float* l3b  = (const float*)d_in[14];
    float*       out  = (float*)d_out;

    float *xw, *h;
    cudaGetSymbolAddress((void**)&xw, g_xw);
    cudaGetSymbolAddress((void**)&h,  g_h);
    __nv_bfloat16 *wbh, *wbl, *w1h, *w1l;
    cudaGetSymbolAddress((void**)&wbh, g_wbh);
    cudaGetSymbolAddress((void**)&wbl, g_wbl);
    cudaGetSymbolAddress((void**)&w1h, g_w1h);
    cudaGetSymbolAddress((void**)&w1l, g_w1l);

    cudaFuncSetAttribute(k_conv_mma, cudaFuncAttributeMaxDynamicSharedMemorySize, SM_MMA_TOT);
    cudaFuncSetAttribute(k_dense_mma, cudaFuncAttributeMaxDynamicSharedMemorySize, DM_TOT);

    const int T = 256;

    // normalization + CSR build + weight images
    k_deg_init<<<(NN + T - 1) / T, T>>>();
    k_deg_acc<<<(EE + T - 1) / T, T>>>(ei, ea);
    k_scan1<<<NBLK, SCAN_BLK>>>();
    k_scan_top<<<1, 128>>>();
    k_scan_add<<<NBLK, SCAN_BLK>>>();
    k_fill<<<(EE + T - 1) / T, T>>>(ei, ea);
    k_wb<<<(512 * 64 + 64 * 64 + T - 1) / T, T>>>(gc0w, gc1w);
    k_wd<<<(14336 + T - 1) / T, T>>>(l0w, l1w, l2w, l3w);

    // conv 0: tensor-core GEMM (K=512)
    k_conv_mma<<<(NN + 127) / 128, T, SM_MMA_TOT>>>(x, xw, NN, IND, wbh, wbl);
    k_gather<<<(NN * 16 + T - 1) / T, T>>>(gc0b);

    // conv 1: tensor-core GEMM (K=64)
    k_conv_mma<<<(NN + 127) / 128, T, SM_MMA_TOT>>>(h, xw, NN, HGD, w1h, w1l);
    k_gather<<<(NN * 16 + T - 1) / T, T>>>(gc1b);

    // dense stack + softmax on tensor cores
    k_dense_mma<<<(NN + 127) / 128, T, DM_TOT>>>(l0b, l1b, l2b, l3b, out, NN);
}

// round 14
// speedup vs baseline: 2.4816x; 1.0732x over previous
#include <cuda_runtime.h>
#include <cuda_bf16.h>
#include <math.h>
#include <stdint.h>

#define NN  100000
#define EE  1600000
#define IND 512
#define HGD 64
#define OUTD 20

#define SCAN_BLK 1024
#define NBLK ((NN + SCAN_BLK - 1) / SCAN_BLK)   // 98

typedef unsigned long long ull;

// ---------------- scratch (static device globals; no allocs) ----------------
__device__ __align__(8) float2 g_dc[NN];  // (deg, cnt) accumulated together
__device__ float g_deg[NN];               // dinv after scan_add
__device__ int   g_rowptr[NN + 1];
__device__ int   g_cursor[NN];
__device__ int   g_bsum[NBLK];
__device__ __align__(8) int2 g_ce[EE];    // CSR: (src, norm-bits) packed
__device__ __align__(16) float g_xw[(size_t)NN * HGD];
__device__ __align__(16) float g_h[(size_t)NN * HGD];
// conv weights split-bf16 images, [n][k] layout
__device__ __align__(16) __nv_bfloat16 g_wbh[64 * 512];   // gc0_w
__device__ __align__(16) __nv_bfloat16 g_wbl[64 * 512];
__device__ __align__(16) __nv_bfloat16 g_w1h[64 * 64];    // gc1_w
__device__ __align__(16) __nv_bfloat16 g_w1l[64 * 64];
// dense weights split-bf16 images: [L][n][k], L=0..2 (64x64), W3 padded 32x64
__device__ __align__(16) __nv_bfloat16 g_wdh[3 * 64 * 64];
__device__ __align__(16) __nv_bfloat16 g_wdl[3 * 64 * 64];
__device__ __align__(16) __nv_bfloat16 g_w3h[32 * 64];
__device__ __align__(16) __nv_bfloat16 g_w3l[32 * 64];

__device__ __forceinline__ float selu_f(float x) {
    const float a = 1.6732632423543772f, s = 1.0507009873554805f;
    return s * (x > 0.f ? x : a * expm1f(x));
}

// warp-level bf16 MMA (sm_80+ PTX)
__device__ __forceinline__ void mma_bf16(float* c, const uint32_t* a, uint32_t b0, uint32_t b1) {
    asm volatile(
        "mma.sync.aligned.m16n8k16.row.col.f32.bf16.bf16.f32 "
        "{%0,%1,%2,%3}, {%4,%5,%6,%7}, {%8,%9}, {%0,%1,%2,%3};"
        : "+f"(c[0]), "+f"(c[1]), "+f"(c[2]), "+f"(c[3])
        : "r"(a[0]), "r"(a[1]), "r"(a[2]), "r"(a[3]), "r"(b0), "r"(b1));
}

__device__ __forceinline__ void ldsm4(uint32_t* r, uint32_t addr) {
    asm volatile("ldmatrix.sync.aligned.m8n8.x4.shared.b16 {%0,%1,%2,%3}, [%4];"
                 : "=r"(r[0]), "=r"(r[1]), "=r"(r[2]), "=r"(r[3]) : "r"(addr));
}

__device__ __forceinline__ uint32_t smem_u32(const void* p) {
    uint32_t a;
    asm("{ .reg .u64 t; cvta.to.shared.u64 t, %1; cvt.u32.u64 %0, t; }" : "=r"(a) : "l"(p));
    return a;
}

// split f32 pair -> packed bf16x2 (hi, lo)
__device__ __forceinline__ void split2(float x, float y, uint32_t& hi, uint32_t& lo) {
    __nv_bfloat16 hx = __float2bfloat16(x), hy = __float2bfloat16(y);
    __nv_bfloat162 h; h.x = hx; h.y = hy;
    __nv_bfloat162 l; l.x = __float2bfloat16(x - __bfloat162float(hx));
                      l.y = __float2bfloat16(y - __bfloat162float(hy));
    hi = *(uint32_t*)&h;
    lo = *(uint32_t*)&l;
}

// ---------------- degree + count ----------------
__global__ void k_deg_init() {
    int i = blockIdx.x * blockDim.x + threadIdx.x;
    if (i < NN) g_dc[i] = make_float2(1.0f, 0.0f);   // self-loop weight 1
}

__global__ void k_deg_acc(const int* __restrict__ ei, const float* __restrict__ w) {
    int e = blockIdx.x * blockDim.x + threadIdx.x;
    if (e < EE) {
        int c = ei[EE + e];
        asm volatile("red.global.add.v2.f32 [%0], {%1, %2};"
                     :: "l"(&g_dc[c]), "f"(w[e]), "f"(1.0f) : "memory");
    }
}

// ---------------- exclusive scan over cnt -> g_rowptr ----------------
__global__ void k_scan1() {
    __shared__ int sh[SCAN_BLK];
    int i = blockIdx.x * SCAN_BLK + threadIdx.x;
    int v = (i < NN) ? (int)g_dc[i].y : 0;
    sh[threadIdx.x] = v;
    __syncthreads();
    for (int off = 1; off < SCAN_BLK; off <<= 1) {
        int t = (threadIdx.x >= off) ? sh[threadIdx.x - off] : 0;
        __syncthreads();
        sh[threadIdx.x] += t;
        __syncthreads();
    }
    if (i < NN) g_rowptr[i] = sh[threadIdx.x] - v;
    if (threadIdx.x == SCAN_BLK - 1) g_bsum[blockIdx.x] = sh[threadIdx.x];
}

// scan_add with inline top-level prefix (sums g_bsum[0..bid-1] per block);
// also computes dinv
__global__ void k_scan_add() {
    __shared__ int sred[128];
    int tidx = threadIdx.x;
    if (tidx < 128)
        sred[tidx] = (tidx < NBLK && tidx < blockIdx.x) ? g_bsum[tidx] : 0;
    __syncthreads();
    if (tidx < 64) sred[tidx] += sred[tidx + 64];
    __syncthreads();
    if (tidx < 32) {
        int s = sred[tidx] + sred[tidx + 32];
        s += __shfl_down_sync(0xffffffffu, s, 16);
        s += __shfl_down_sync(0xffffffffu, s, 8);
        s += __shfl_down_sync(0xffffffffu, s, 4);
        s += __shfl_down_sync(0xffffffffu, s, 2);
        s += __shfl_down_sync(0xffffffffu, s, 1);
        if (tidx == 0) sred[0] = s;
    }
    __syncthreads();
    int prefix = sred[0];

    int i = blockIdx.x * SCAN_BLK + tidx;
    if (i < NN) {
        int r = g_rowptr[i] + prefix;
        g_rowptr[i] = r;
        g_cursor[i] = r;
        float d = g_dc[i].x;
        g_deg[i] = d > 0.f ? rsqrtf(fmaxf(d, 1e-30f)) : 0.f;
    }
    if (i == 0) g_rowptr[NN] = EE;
}

// ---------------- CSR fill (packed int2) ----------------
__global__ void k_fill(const int* __restrict__ ei, const float* __restrict__ w) {
    int e = blockIdx.x * blockDim.x + threadIdx.x;
    if (e < EE) {
        int r = ei[e];
        int c = ei[EE + e];
        int pos = atomicAdd(&g_cursor[c], 1);
        float nm = g_deg[r] * w[e] * g_deg[c];
        g_ce[pos] = make_int2(r, __float_as_int(nm));
    }
}

// ---------------- conv weights -> split-bf16 images, [n][k] -----------------
__global__ void k_wb(const float* __restrict__ W0, const float* __restrict__ W1) {
    int i = blockIdx.x * blockDim.x + threadIdx.x;
    if (i < 512 * 64) {
        int k = i >> 6, n = i & 63;
        float w = W0[i];
        __nv_bfloat16 hi = __float2bfloat16(w);
        __nv_bfloat16 lo = __float2bfloat16(w - __bfloat162float(hi));
        g_wbh[n * 512 + k] = hi;
        g_wbl[n * 512 + k] = lo;
    } else if (i < 512 * 64 + 64 * 64) {
        int r = i - 512 * 64;
        int k = r >> 6, n = r & 63;
        float w = W1[r];
        __nv_bfloat16 hi = __float2bfloat16(w);
        __nv_bfloat16 lo = __float2bfloat16(w - __bfloat162float(hi));
        g_w1h[n * 64 + k] = hi;
        g_w1l[n * 64 + k] = lo;
    }
}

// ---------------- dense weights -> split-bf16 images ------------------------
__global__ void k_wd(const float* __restrict__ w0, const float* __restrict__ w1,
                     const float* __restrict__ w2, const float* __restrict__ w3) {
    int i = blockIdx.x * blockDim.x + threadIdx.x;
    if (i < 3 * 4096) {
        int L = i >> 12, r = i & 4095;
        int k = r >> 6, n = r & 63;
        const float* W = (L == 0) ? w0 : ((L == 1) ? w1 : w2);
        float v = W[k * 64 + n];
        __nv_bfloat16 hi = __float2bfloat16(v);
        __nv_bfloat16 lo = __float2bfloat16(v - __bfloat162float(hi));
        g_wdh[L * 4096 + n * 64 + k] = hi;
        g_wdl[L * 4096 + n * 64 + k] = lo;
    } else if (i < 3 * 4096 + 2048) {
        int r = i - 12288;
        int n = r >> 6, k = r & 63;
        float v = (n < 20) ? w3[k * 20 + n] : 0.f;
        __nv_bfloat16 hi = __float2bfloat16(v);
        __nv_bfloat16 lo = __float2bfloat16(v - __bfloat162float(hi));
        g_w3h[n * 64 + k] = hi;
        g_w3l[n * 64 + k] = lo;
    }
}

// ---------------- generic conv GEMM on mma.sync (split-bf16, ldmatrix) -----
#define ASTR 72
#define SM_AHI_O 0
#define SM_ALO_O 18432
#define SM_BHI_O 36864
#define SM_BLO_O 46080
#define SM_MMA_TOT 55296
__global__ void k_conv_mma(const float* __restrict__ A, float* __restrict__ C, int M, int K,
                           const __nv_bfloat16* __restrict__ WH,
                           const __nv_bfloat16* __restrict__ WL) {
    extern __shared__ __align__(16) char smem[];
    __nv_bfloat16* Ah = (__nv_bfloat16*)(smem + SM_AHI_O);
    __nv_bfloat16* Al = (__nv_bfloat16*)(smem + SM_ALO_O);
    __nv_bfloat16* Bh = (__nv_bfloat16*)(smem + SM_BHI_O);
    __nv_bfloat16* Bl = (__nv_bfloat16*)(smem + SM_BLO_O);

    int tid = threadIdx.x;
    int w = tid >> 5, lane = tid & 31;
    int gr = lane >> 2, t = lane & 3;
    int row0 = blockIdx.x * 128;
    uint32_t sb = smem_u32(smem);

    uint32_t a_off = (uint32_t)((w * 16 + (lane & 7) + ((lane >> 3) & 1) * 8) * 144
                                + ((lane >> 4) & 1) * 16);
    uint32_t b_off_base = (uint32_t)((((lane >> 4) & 1) * 8 + (lane & 7)) * 144
                                     + ((lane >> 3) & 1) * 16);

    float acc[8][4];
#pragma unroll
    for (int i = 0; i < 8; i++)
#pragma unroll
        for (int j = 0; j < 4; j++) acc[i][j] = 0.f;

    int chunks = K >> 6;
    for (int c = 0; c < chunks; c++) {
#pragma unroll
        for (int it = 0; it < 8; it++) {
            int idx = tid + it * 256;
            int r = idx >> 4;
            int kq = (idx & 15) * 4;
            int row = row0 + r;
            float4 v = (row < M) ? *(const float4*)&A[(size_t)row * K + c * 64 + kq]
                                 : make_float4(0.f, 0.f, 0.f, 0.f);
            uint32_t h0, l0, h1, l1;
            split2(v.x, v.y, h0, l0);
            split2(v.z, v.w, h1, l1);
            int so = r * ASTR + kq;
            *(uint32_t*)(Ah + so)     = h0;
            *(uint32_t*)(Ah + so + 2) = h1;
            *(uint32_t*)(Al + so)     = l0;
            *(uint32_t*)(Al + so + 2) = l1;
        }
#pragma unroll
        for (int it = 0; it < 2; it++) {
            int i = tid + it * 256;
            int n = i >> 3, j = i & 7;
            uint4 vh = *((const uint4*)(WH + (size_t)n * K + c * 64) + j);
            uint4 vl = *((const uint4*)(WL + (size_t)n * K + c * 64) + j);
            *((uint4*)((char*)Bh + n * 144) + j) = vh;
            *((uint4*)((char*)Bl + n * 144) + j) = vl;
        }
        __syncthreads();

#pragma unroll
        for (int ks = 0; ks < 4; ks++) {
            uint32_t kadd = (uint32_t)(ks * 32);
            uint32_t ah[4], al[4];
            ldsm4(ah, sb + SM_AHI_O + a_off + kadd);
            ldsm4(al, sb + SM_ALO_O + a_off + kadd);
#pragma unroll
            for (int p = 0; p < 4; p++) {
                uint32_t boff = b_off_base + (uint32_t)(p * 16 * 144) + kadd;
                uint32_t bh[4], bl[4];
                ldsm4(bh, sb + SM_BHI_O + boff);
                ldsm4(bl, sb + SM_BLO_O + boff);
                mma_bf16(acc[2 * p],     ah, bh[0], bh[1]);
                mma_bf16(acc[2 * p],     al, bh[0], bh[1]);
                mma_bf16(acc[2 * p],     ah, bl[0], bl[1]);
                mma_bf16(acc[2 * p + 1], ah, bh[2], bh[3]);
                mma_bf16(acc[2 * p + 1], al, bh[2], bh[3]);
                mma_bf16(acc[2 * p + 1], ah, bl[2], bl[3]);
            }
        }
        __syncthreads();
    }

    int r1 = row0 + w * 16 + gr;
    int r2 = r1 + 8;
#pragma unroll
    for (int nt = 0; nt < 8; nt++) {
        int col = nt * 8 + t * 2;
        if (r1 < M) *(float2*)&C[(size_t)r1 * 64 + col] = make_float2(acc[nt][0], acc[nt][1]);
        if (r2 < M) *(float2*)&C[(size_t)r2 * 64 + col] = make_float2(acc[nt][2], acc[nt][3]);
    }
}

// ---------------- CSR gather + self-loop + bias + SELU -> g_h --------------
__global__ void k_gather(const float* __restrict__ bias) {
    int t = blockIdx.x * blockDim.x + threadIdx.x;
    if (t >= NN * 16) return;
    int n = t >> 4;
    int q = (t & 15) << 2;

    float d = g_deg[n];
    float dd = d * d;
    float4 v = *(const float4*)&g_xw[(size_t)n * 64 + q];
    float4 acc = make_float4(v.x * dd, v.y * dd, v.z * dd, v.w * dd);

    int s = g_rowptr[n], e2 = g_rowptr[n + 1];
    int i = s;
    for (; i + 1 < e2; i += 2) {
        int2 p0 = g_ce[i];
        int2 p1 = g_ce[i + 1];
        float n0 = __int_as_float(p0.y), n1 = __int_as_float(p1.y);
        float4 u0 = *(const float4*)&g_xw[(size_t)p0.x * 64 + q];
        float4 u1 = *(const float4*)&g_xw[(size_t)p1.x * 64 + q];
        acc.x += n0 * u0.x + n1 * u1.x;
        acc.y += n0 * u0.y + n1 * u1.y;
        acc.z += n0 * u0.z + n1 * u1.z;
        acc.w += n0 * u0.w + n1 * u1.w;
    }
    if (i < e2) {
        int2 p0 = g_ce[i];
        float n0 = __int_as_float(p0.y);
        float4 u0 = *(const float4*)&g_xw[(size_t)p0.x * 64 + q];
        acc.x += n0 * u0.x;
        acc.y += n0 * u0.y;
        acc.z += n0 * u0.z;
        acc.w += n0 * u0.w;
    }

    float4 b4 = *(const float4*)&bias[q];
    float4 o;
    o.x = selu_f(acc.x + b4.x);
    o.y = selu_f(acc.y + b4.y);
    o.z = selu_f(acc.z + b4.z);
    o.w = selu_f(acc.w + b4.w);
    *(float4*)&g_h[(size_t)n * 64 + q] = o;
}

// ---------------- dense MLP on mma.sync: 3x(64x64)+SELU, 64x20, softmax ----
#define DM_AH 0
#define DM_AL 18432
#define DM_BH 36864
#define DM_BL 46080
#define DM_BS 55296
#define DM_TOT 55552
__global__ void k_dense_mma(const float* __restrict__ b0, const float* __restrict__ b1,
                            const float* __restrict__ b2, const float* __restrict__ b3,
                            float* __restrict__ out, int M) {
    extern __shared__ __align__(16) char smem[];
    __nv_bfloat16* Ah = (__nv_bfloat16*)(smem + DM_AH);
    __nv_bfloat16* Al = (__nv_bfloat16*)(smem + DM_AL);
    float* bs = (float*)(smem + DM_BS);

    int tid = threadIdx.x;
    int w = tid >> 5, lane = tid & 31;
    int gr = lane >> 2, t = lane & 3;
    int row0 = blockIdx.x * 128;
    uint32_t sb = smem_u32(smem);

    uint32_t a_off = (uint32_t)((w * 16 + (lane & 7) + ((lane >> 3) & 1) * 8) * 144
                                + ((lane >> 4) & 1) * 16);
    uint32_t b_off_base = (uint32_t)((((lane >> 4) & 1) * 8 + (lane & 7)) * 144
                                     + ((lane >> 3) & 1) * 16);

    // initial A: g_h -> split bf16 smem
#pragma unroll
    for (int it = 0; it < 8; it++) {
        int idx = tid + it * 256;
        int r = idx >> 4;
        int kq = (idx & 15) * 4;
        int row = row0 + r;
        float4 v = (row < M) ? *(const float4*)&g_h[(size_t)row * 64 + kq]
                             : make_float4(0.f, 0.f, 0.f, 0.f);
        uint32_t h0, l0, h1, l1;
        split2(v.x, v.y, h0, l0);
        split2(v.z, v.w, h1, l1);
        int so = r * ASTR + kq;
        *(uint32_t*)(Ah + so)     = h0;
        *(uint32_t*)(Ah + so + 2) = h1;
        *(uint32_t*)(Al + so)     = l0;
        *(uint32_t*)(Al + so + 2) = l1;
    }

    const float* Bp[3] = {b0, b1, b2};

    for (int L = 0; L < 3; L++) {
#pragma unroll
        for (int it = 0; it < 2; it++) {
            int i = tid + it * 256;
            int n = i >> 3, j = i & 7;
            uint4 vh = *((const uint4*)(g_wdh + L * 4096 + n * 64) + j);
            uint4 vl = *((const uint4*)(g_wdl + L * 4096 + n * 64) + j);
            *((uint4*)(smem + DM_BH + n * 144) + j) = vh;
            *((uint4*)(smem + DM_BL + n * 144) + j) = vl;
        }
        if (tid < 64) bs[tid] = Bp[L][tid];
        __syncthreads();

        float acc[8][4];
#pragma unroll
        for (int i = 0; i < 8; i++)
#pragma unroll
            for (int j = 0; j < 4; j++) acc[i][j] = 0.f;

#pragma unroll
        for (int ks = 0; ks < 4; ks++) {
            uint32_t kadd = (uint32_t)(ks * 32);
            uint32_t ah[4], al[4];
            ldsm4(ah, sb + DM_AH + a_off + kadd);
            ldsm4(al, sb + DM_AL + a_off + kadd);
#pragma unroll
            for (int p = 0; p < 4; p++) {
                uint32_t boff = b_off_base + (uint32_t)(p * 16 * 144) + kadd;
                uint32_t bh[4], bl[4];
                ldsm4(bh, sb + DM_BH + boff);
                ldsm4(bl, sb + DM_BL + boff);
                mma_bf16(acc[2 * p],     ah, bh[0], bh[1]);
                mma_bf16(acc[2 * p],     al, bh[0], bh[1]);
                mma_bf16(acc[2 * p],     ah, bl[0], bl[1]);
                mma_bf16(acc[2 * p + 1], ah, bh[2], bh[3]);
                mma_bf16(acc[2 * p + 1], al, bh[2], bh[3]);
                mma_bf16(acc[2 * p + 1], ah, bl[2], bl[3]);
            }
        }

        uint32_t whi[8][2], wlo[8][2];
#pragma unroll
        for (int nt = 0; nt < 8; nt++) {
            float2 bb = *(const float2*)&bs[nt * 8 + 2 * t];
            float c0 = selu_f(acc[nt][0] + bb.x);
            float c1 = selu_f(acc[nt][1] + bb.y);
            float c2 = selu_f(acc[nt][2] + bb.x);
            float c3 = selu_f(acc[nt][3] + bb.y);
            split2(c0, c1, whi[nt][0], wlo[nt][0]);
            split2(c2, c3, whi[nt][1], wlo[nt][1]);
        }
        __syncthreads();
        int ra = (w * 16 + gr) * ASTR;
        int rb = (w * 16 + gr + 8) * ASTR;
#pragma unroll
        for (int nt = 0; nt < 8; nt++) {
            int co = nt * 8 + 2 * t;
            *(uint32_t*)(Ah + ra + co) = whi[nt][0];
            *(uint32_t*)(Al + ra + co) = wlo[nt][0];
            *(uint32_t*)(Ah + rb + co) = whi[nt][1];
            *(uint32_t*)(Al + rb + co) = wlo[nt][1];
        }
        __syncthreads();
    }

    // final layer: W3 padded to 32 rows
    {
        int i = tid;
        int n = i >> 3, j = i & 7;
        uint4 vh = *((const uint4*)(g_w3h + n * 64) + j);
        uint4 vl = *((const uint4*)(g_w3l + n * 64) + j);
        *((uint4*)(smem + DM_BH + n * 144) + j) = vh;
        *((uint4*)(smem + DM_BL + n * 144) + j) = vl;
    }
    if (tid < 24) bs[tid] = (tid < 20) ? b3[tid] : 0.f;
    __syncthreads();

    float accf[4][4];
#pragma unroll
    for (int i = 0; i < 4; i++)
#pragma unroll
        for (int j = 0; j < 4; j++) accf[i][j] = 0.f;

#pragma unroll
    for (int ks = 0; ks < 4; ks++) {
        uint32_t kadd = (uint32_t)(ks * 32);
        uint32_t ah[4], al[4];
        ldsm4(ah, sb + DM_AH + a_off + kadd);
        ldsm4(al, sb + DM_AL + a_off + kadd);
#pragma unroll
        for (int p = 0; p < 2; p++) {
            uint32_t boff = b_off_base + (uint32_t)(p * 16 * 144) + kadd;
            uint32_t bh[4], bl[4];
            ldsm4(bh, sb + DM_BH + boff);
            ldsm4(bl, sb + DM_BL + boff);
            mma_bf16(accf[2 * p],     ah, bh[0], bh[1]);
            mma_bf16(accf[2 * p],     al, bh[0], bh[1]);
            mma_bf16(accf[2 * p],     ah, bl[0], bl[1]);
            mma_bf16(accf[2 * p + 1], ah, bh[2], bh[3]);
            mma_bf16(accf[2 * p + 1], al, bh[2], bh[3]);
            mma_bf16(accf[2 * p + 1], ah, bl[2], bl[3]);
        }
    }

    float lg0[6], lg1[6];
#pragma unroll
    for (int nt = 0; nt < 3; nt++) {
        float2 bb = *(const float2*)&bs[nt * 8 + 2 * t];
        lg0[2 * nt]     = accf[nt][0] + bb.x;
        lg0[2 * nt + 1] = accf[nt][1] + bb.y;
        lg1[2 * nt]     = accf[nt][2] + bb.x;
        lg1[2 * nt + 1] = accf[nt][3] + bb.y;
    }
    bool v4 = (16 + 2 * t) < 20;
    if (!v4) { lg0[4] = lg0[5] = lg1[4] = lg1[5] = -1e30f; }

    float m0 = lg0[0], m1 = lg1[0];
#pragma unroll
    for (int i = 1; i < 6; i++) { m0 = fmaxf(m0, lg0[i]); m1 = fmaxf(m1, lg1[i]); }
    m0 = fmaxf(m0, __shfl_xor_sync(0xffffffffu, m0, 1));
    m0 = fmaxf(m0, __shfl_xor_sync(0xffffffffu, m0, 2));
    m1 = fmaxf(m1, __shfl_xor_sync(0xffffffffu, m1, 1));
    m1 = fmaxf(m1, __shfl_xor_sync(0xffffffffu, m1, 2));

    float e0[6], e1[6], s0 = 0.f, s1 = 0.f;
#pragma unroll
    for (int i = 0; i < 6; i++) {
        e0[i] = expf(lg0[i] - m0);
        e1[i] = expf(lg1[i] - m1);
        s0 += e0[i];
        s1 += e1[i];
    }
    s0 += __shfl_xor_sync(0xffffffffu, s0, 1);
    s0 += __shfl_xor_sync(0xffffffffu, s0, 2);
    s1 += __shfl_xor_sync(0xffffffffu, s1, 1);
    s1 += __shfl_xor_sync(0xffffffffu, s1, 2);
    float i0 = 1.f / s0, i1 = 1.f / s1;

    int r1 = row0 + w * 16 + gr;
    int r2 = r1 + 8;
#pragma unroll
    for (int nt = 0; nt < 3; nt++) {
        if (nt == 2 && !v4) continue;
        int col = nt * 8 + 2 * t;
        if (r1 < M) *(float2*)&out[(size_t)r1 * 20 + col] = make_float2(e0[2 * nt] * i0, e0[2 * nt + 1] * i0);
        if (r2 < M) *(float2*)&out[(size_t)r2 * 20 + col] = make_float2(e1[2 * nt] * i1, e1[2 * nt + 1] * i1);
    }
}

// ---------------- launch ----------------
extern "C" void kernel_launch(void* const* d_in, const int* in_sizes, int n_in,
                              void* d_out, int out_size) {
    const float* x    = (const float*)d_in[0];
    const int*   ei   = (const int*)d_in[1];      // int32 (JAX x64 disabled)
    const float* ea   = (const float*)d_in[2];
    const float* gc0w = (const float*)d_in[3];
    const float* gc0b = (const float*)d_in[4];
    const float* gc1w = (const float*)d_in[5];
    const float* gc1b = (const float*)d_in[6];
    const float* l0w  = (const float*)d_in[7];
    const float* l0b  = (const float*)d_in[8];
    const float* l1w  = (const float*)d_in[9];
    const float* l1b  = (const float*)d_in[10];
    const float* l2w  = (const float*)d_in[11];
    const float* l2b  = (const float*)d_in[12];
    const float* l3w  = (const float*)d_in[13];
    const float* l3b  = (const float*)d_in[14];
    float*       out  = (float*)d_out;

    float *xw, *h;
    cudaGetSymbolAddress((void**)&xw, g_xw);
    cudaGetSymbolAddress((void**)&h,  g_h);
    __nv_bfloat16 *wbh, *wbl, *w1h, *w1l;
    cudaGetSymbolAddress((void**)&wbh, g_wbh);
    cudaGetSymbolAddress((void**)&wbl, g_wbl);
    cudaGetSymbolAddress((void**)&w1h, g_w1h);
    cudaGetSymbolAddress((void**)&w1l, g_w1l);

    cudaFuncSetAttribute(k_conv_mma, cudaFuncAttributeMaxDynamicSharedMemorySize, SM_MMA_TOT);
    cudaFuncSetAttribute(k_dense_mma, cudaFuncAttributeMaxDynamicSharedMemorySize, DM_TOT);

    // second stream + fork/join events (host-side objects, created once)
    static cudaStream_t s2 = nullptr;
    static cudaEvent_t ev_fork = nullptr, ev_join = nullptr;
    if (s2 == nullptr) {
        cudaStreamCreateWithFlags(&s2, cudaStreamNonBlocking);
        cudaEventCreateWithFlags(&ev_fork, cudaEventDisableTiming);
        cudaEventCreateWithFlags(&ev_join, cudaEventDisableTiming);
    }

    const int T = 256;

    // fork: branch B (weight images + conv0 GEMM) on s2
    cudaEventRecord(ev_fork, 0);
    cudaStreamWaitEvent(s2, ev_fork, 0);
    k_wb<<<(512 * 64 + 64 * 64 + T - 1) / T, T, 0, s2>>>(gc0w, gc1w);
    k_wd<<<(14336 + T - 1) / T, T, 0, s2>>>(l0w, l1w, l2w, l3w);
    k_conv_mma<<<(NN + 127) / 128, T, SM_MMA_TOT, s2>>>(x, xw, NN, IND, wbh, wbl);
    cudaEventRecord(ev_join, s2);

    // branch A (CSR build) on default stream
    k_deg_init<<<(NN + T - 1) / T, T>>>();
    k_deg_acc<<<(EE + T - 1) / T, T>>>(ei, ea);
    k_scan1<<<NBLK, SCAN_BLK>>>();
    k_scan_add<<<NBLK, SCAN_BLK>>>();
    k_fill<<<(EE + T - 1) / T, T>>>(ei, ea);

    // join: gather0 needs CSR (branch A) + xw (branch B)
    cudaStreamWaitEvent(0, ev_join, 0);
    k_gather<<<(NN * 16 + T - 1) / T, T>>>(gc0b);

    // conv 1 (K=64) + gather 1
    k_conv_mma<<<(NN + 127) / 128, T, SM_MMA_TOT>>>(h, xw, NN, HGD, w1h, w1l);
    k_gather<<<(NN * 16 + T - 1) / T, T>>>(gc1b);

    // dense stack + softmax on tensor cores
    k_dense_mma<<<(NN + 127) / 128, T, DM_TOT>>>(l0b, l1b, l2b, l3b, out, NN);
}